// round 7
// baseline (speedup 1.0000x reference)
#include <cuda_runtime.h>
#include <cuda_bf16.h>
#include <cuda_fp16.h>
#include <cstdint>

// Problem constants (fixed by the dataset)
#define BB   8
#define LQ   5440
#define LIN  5440
#define DM   256
#define NH   8
#define MTOT (BB * LQ)   // 43520

// ---------------------------------------------------------------------------
// Scratch (device globals; allocation-free per harness rules)
// ---------------------------------------------------------------------------
__device__ __align__(16) float g_value[MTOT * DM];          // fp32 value
__device__ __align__(16) float g_oa  [MTOT * 384];          // off(256) + attn logits(128)
__device__ __align__(16) float g_core[MTOT * DM];

// Pre-split / pre-transposed weights, chunk-contiguous bf16 layout:
// element index = ((k>>6)*N + n)*64 + (k&63)   (64-wide K chunks)
__device__ __align__(16) __nv_bfloat16 g_wv_hi [DM * DM],  g_wv_lo [DM * DM];
__device__ __align__(16) __nv_bfloat16 g_woa_hi[DM * 384], g_woa_lo[DM * 384];
__device__ __align__(16) __nv_bfloat16 g_wu_hi [DM * DM],  g_wu_lo [DM * DM];
__device__ __align__(16) float g_boa[384];

// ---------------------------------------------------------------------------
// Helpers (base-target ISA only: ldmatrix / cp.async / mma.sync)
// ---------------------------------------------------------------------------
__device__ __forceinline__ uint32_t smem_u32(const void* p) {
    uint32_t a;
    asm("{ .reg .u64 t; cvta.to.shared.u64 t, %1; cvt.u32.u64 %0, t; }"
        : "=r"(a) : "l"(p));
    return a;
}
__device__ __forceinline__ void ldsm4(uint32_t* d, uint32_t addr) {
    asm volatile("ldmatrix.sync.aligned.m8n8.x4.shared.b16 {%0,%1,%2,%3}, [%4];"
                 : "=r"(d[0]), "=r"(d[1]), "=r"(d[2]), "=r"(d[3]) : "r"(addr));
}
__device__ __forceinline__ void mma16816(float* c, const uint32_t* a,
                                         const uint32_t* b) {
    asm volatile(
        "mma.sync.aligned.m16n8k16.row.col.f32.bf16.bf16.f32 "
        "{%0,%1,%2,%3}, {%4,%5,%6,%7}, {%8,%9}, {%0,%1,%2,%3};"
        : "+f"(c[0]), "+f"(c[1]), "+f"(c[2]), "+f"(c[3])
        : "r"(a[0]), "r"(a[1]), "r"(a[2]), "r"(a[3]), "r"(b[0]), "r"(b[1]));
}
__device__ __forceinline__ void cp16(uint32_t dst, const void* src) {
    asm volatile("cp.async.cg.shared.global [%0], [%1], 16;"
                 :: "r"(dst), "l"(src) : "memory");
}
__device__ __forceinline__ uint32_t sw128(uint32_t b) { return b ^ ((b >> 3) & 0x70); }

// ---------------------------------------------------------------------------
// Fused weight prep: all three weight matrices (val / off+attn combined / out)
// transposed + bf16 hi/lo split into chunk-contiguous layout, plus combined bias.
// ---------------------------------------------------------------------------
__global__ void prep_all(const float* __restrict__ W_val,
                         const float* __restrict__ W_off,
                         const float* __restrict__ W_attn,
                         const float* __restrict__ W_out,
                         const float* __restrict__ b_off,
                         const float* __restrict__ b_attn)
{
    __nv_bfloat16 *wv_h = g_wv_hi,  *wv_l = g_wv_lo;
    __nv_bfloat16 *wa_h = g_woa_hi, *wa_l = g_woa_lo;
    __nv_bfloat16 *wu_h = g_wu_hi,  *wu_l = g_wu_lo;

    int idx = blockIdx.x * 256 + threadIdx.x;
    if (idx < 384)
        g_boa[idx] = idx < 256 ? b_off[idx] : b_attn[idx - 256];

    float v; __nv_bfloat16 *hi, *lo; int o;
    if (idx < 65536) {                       // W_val [256x256]
        int k = idx >> 8, n = idx & 255;
        v = W_val[idx];
        o = (((k >> 6) << 8) + n) * 64 + (k & 63);
        hi = wv_h; lo = wv_l;
    } else if (idx < 65536 + 98304) {        // combined [256x384]
        int t = idx - 65536;
        int k = t / 384, n = t - k * 384;
        v = n < 256 ? W_off[k * 256 + n] : W_attn[k * 128 + (n - 256)];
        o = ((k >> 6) * 384 + n) * 64 + (k & 63);
        hi = wa_h; lo = wa_l;
    } else {                                 // W_out [256x256]
        int t = idx - 65536 - 98304;
        int k = t >> 8, n = t & 255;
        v = W_out[t];
        o = (((k >> 6) << 8) + n) * 64 + (k & 63);
        hi = wu_h; lo = wu_l;
    }
    __nv_bfloat16 h = __float2bfloat16(v);
    hi[o] = h;
    lo[o] = __float2bfloat16(v - __bfloat162float(h));
}

// ---------------------------------------------------------------------------
// mma.sync bf16 GEMM, 3-term split: C[M,N] = A[M,256]*W + bias (fp32-grade).
// CTA: 128x64 tile, 256 thr (8 warps; warp tile 32x32). K: 4 chunks of 64,
// double-buffered smem (48KB/buffer, 96KB total -> 2 CTAs/SM).
// ---------------------------------------------------------------------------
template <int N>
__global__ __launch_bounds__(256, 2) void gemm_mma(
    const float* __restrict__ A,
    const __nv_bfloat16* __restrict__ Bh_g, const __nv_bfloat16* __restrict__ Bl_g,
    const float* __restrict__ bias, float* __restrict__ C)
{
    extern __shared__ char smem[];
    constexpr int BUF = 49152;
    constexpr int O_AL = 16384, O_BH = 32768, O_BL = 40960;

    const int tid  = threadIdx.x;
    const int wid  = tid >> 5;
    const int lane = tid & 31;
    const int mBase = blockIdx.y * 128;
    const int nBase = blockIdx.x * 64;
    const int warpM = (wid & 3) * 32;
    const int warpN = (wid >> 2) * 32;

    const float4* Ag  = (const float4*)A;
    const uint4*  Bhg = (const uint4*)Bh_g;
    const uint4*  Blg = (const uint4*)Bl_g;

    float acc[2][4][4];
#pragma unroll
    for (int i = 0; i < 2; i++)
#pragma unroll
        for (int j = 0; j < 4; j++)
#pragma unroll
            for (int k = 0; k < 4; k++) acc[i][j][k] = 0.f;

    auto loadB = [&](int c, char* buf) {
        uint32_t bh = smem_u32(buf + O_BH), bl = smem_u32(buf + O_BL);
#pragma unroll
        for (int i = 0; i < 2; i++) {
            int f = tid + 256 * i;
            int n = f >> 3, u = f & 7;
            uint32_t so = (n << 7) + (((u ^ (n & 7))) << 4);
            size_t gi = (size_t)(c * N + nBase + n) * 8 + u;
            cp16(bh + so, Bhg + gi);
            cp16(bl + so, Blg + gi);
        }
        asm volatile("cp.async.commit_group;" ::: "memory");
    };

    float4 apf[8];
    auto loadA = [&](int c) {
#pragma unroll
        for (int i = 0; i < 8; i++) {
            int f = tid + 256 * i;
            int row = f >> 4, q = f & 15;
            apf[i] = Ag[(size_t)(mBase + row) * 64 + c * 16 + q];
        }
    };
    auto storeA = [&](char* buf) {
        char* ah = buf;
        char* al = buf + O_AL;
#pragma unroll
        for (int i = 0; i < 8; i++) {
            int f = tid + 256 * i;
            int row = f >> 4, q = f & 15;
            float4 v = apf[i];
            __nv_bfloat162 h0 = __floats2bfloat162_rn(v.x, v.y);
            __nv_bfloat162 h1 = __floats2bfloat162_rn(v.z, v.w);
            float2 f0 = __bfloat1622float2(h0), f1 = __bfloat1622float2(h1);
            __nv_bfloat162 l0 = __floats2bfloat162_rn(v.x - f0.x, v.y - f0.y);
            __nv_bfloat162 l1 = __floats2bfloat162_rn(v.z - f1.x, v.w - f1.y);
            uint32_t so = sw128(row * 128 + q * 8);
            *(__nv_bfloat162*)(ah + so)     = h0;
            *(__nv_bfloat162*)(ah + so + 4) = h1;
            *(__nv_bfloat162*)(al + so)     = l0;
            *(__nv_bfloat162*)(al + so + 4) = l1;
        }
    };

    loadB(0, smem);
    loadA(0);

    for (int c = 0; c < 4; c++) {
        char* buf = smem + (c & 1) * BUF;
        storeA(buf);
        if (c < 3) loadB(c + 1, smem + ((c + 1) & 1) * BUF);
        if (c < 3) asm volatile("cp.async.wait_group 1;" ::: "memory");
        else       asm volatile("cp.async.wait_group 0;" ::: "memory");
        __syncthreads();
        if (c < 3) loadA(c + 1);

        const uint32_t Ah = smem_u32(buf);
        const uint32_t Al = Ah + O_AL;
        const uint32_t Bh = Ah + O_BH;
        const uint32_t Bl = Ah + O_BL;

#pragma unroll
        for (int kk = 0; kk < 4; kk++) {
            uint32_t ah[2][4], al[2][4];
#pragma unroll
            for (int mi = 0; mi < 2; mi++) {
                int r = warpM + mi * 16 + (lane & 15);
                int u = kk * 2 + (lane >> 4);
                uint32_t off = (r << 7) + (((u ^ (r & 7))) << 4);
                ldsm4(ah[mi], Ah + off);
                ldsm4(al[mi], Al + off);
            }
            uint32_t bh[4][2], bl[4][2];
#pragma unroll
            for (int p = 0; p < 2; p++) {
                int r = warpN + p * 16 + ((lane >> 4) << 3) + (lane & 7);
                int u = kk * 2 + ((lane >> 3) & 1);
                uint32_t off = (r << 7) + (((u ^ (r & 7))) << 4);
                ldsm4(&bh[p * 2][0], Bh + off);
                ldsm4(&bl[p * 2][0], Bl + off);
            }
#pragma unroll
            for (int mi = 0; mi < 2; mi++)
#pragma unroll
                for (int j = 0; j < 4; j++) {
                    float* cc = acc[mi][j];
                    mma16816(cc, ah[mi], bh[j]);
                    mma16816(cc, ah[mi], bl[j]);
                    mma16816(cc, al[mi], bh[j]);
                }
        }
        __syncthreads();
    }

    // ---- epilogue: bias + store ----
#pragma unroll
    for (int mi = 0; mi < 2; mi++) {
        int row0 = mBase + warpM + mi * 16 + (lane >> 2);
#pragma unroll
        for (int nj = 0; nj < 4; nj++) {
            int col = nBase + warpN + nj * 8 + (lane & 3) * 2;
            float bx = __ldg(bias + col), by = __ldg(bias + col + 1);
            *(float2*)(C + (size_t)row0 * N + col) =
                make_float2(acc[mi][nj][0] + bx, acc[mi][nj][1] + by);
            *(float2*)(C + (size_t)(row0 + 8) * N + col) =
                make_float2(acc[mi][nj][2] + bx, acc[mi][nj][3] + by);
        }
    }
}

// ---------------------------------------------------------------------------
// Fused softmax + deformable sampling.
// Block = 256 threads = 4 query rows x 8 heads = 32 head-slots.
// Phase 1 (x2 loop): thread computes softmax'd bilinear weights + byte
//   offsets for one (head-slot, point) -> smem, layout [point][slot] so a
//   warp's 4 slots are 64B-contiguous (broadcast-friendly).
// Phase 2: warp serves 4 head-slots (8 lanes each); lane owns 4 channels via
//   one float4 gather per corner. 16 pts x (2 LDS.128 + 4 LDG.128 + 16 FFMA).
// ---------------------------------------------------------------------------
__global__ __launch_bounds__(256) void msda_sample(const float* __restrict__ refp)
{
    __shared__ float4 sw[16][32];
    __shared__ int4   si[16][32];

    const int tid = threadIdx.x;
    const int rowBase = blockIdx.x * 4;

    // ---- Phase 1: per-(head-slot, point) setup, 512 items / 256 threads ----
#pragma unroll
    for (int j = 0; j < 2; j++) {
        const int hs  = (tid >> 4) + j * 16;   // head slot 0..31
        const int s   = tid & 15;              // point (lvl*4 + pt)
        const int row = rowBase + (hs >> 3);
        const int h   = hs & 7;
        const int b   = row / LQ;

        const int lvl = s >> 2;
        const int Wl  = 64 >> lvl;
        const int st  = (16384 - (16384 >> (2 * lvl))) / 3;

        const float refx = refp[row * 8 + lvl * 2 + 0];
        const float refy = refp[row * 8 + lvl * 2 + 1];
        const int obase  = row * 384 + ((h * 16 + s) * 2);
        const float offx = g_oa[obase + 0];
        const float offy = g_oa[obase + 1];

        const float x = refx * (float)Wl + offx - 0.5f;
        const float y = refy * (float)Wl + offy - 0.5f;
        const float fx = floorf(x), fy = floorf(y);
        const float lx = x - fx,   ly = y - fy;
        const int x0 = (int)fx, y0 = (int)fy;
        const int x1 = x0 + 1,  y1 = y0 + 1;

        const float logit = g_oa[row * 384 + 256 + h * 16 + s];
        float mx = logit;
#pragma unroll
        for (int o = 8; o; o >>= 1) mx = fmaxf(mx, __shfl_xor_sync(~0u, mx, o, 16));
        const float e = __expf(logit - mx);
        float sum = e;
#pragma unroll
        for (int o = 8; o; o >>= 1) sum += __shfl_xor_sync(~0u, sum, o, 16);
        const float wa = e / sum;

        const bool vx0 = (unsigned)x0 < (unsigned)Wl;
        const bool vx1 = (unsigned)x1 < (unsigned)Wl;
        const bool vy0 = (unsigned)y0 < (unsigned)Wl;
        const bool vy1 = (unsigned)y1 < (unsigned)Wl;
        const int cx0 = min(max(x0, 0), Wl - 1);
        const int cx1 = min(max(x1, 0), Wl - 1);
        const int cy0 = min(max(y0, 0), Wl - 1);
        const int cy1 = min(max(y1, 0), Wl - 1);
        const int rb  = b * LIN + st;

        // byte offsets into g_value (row stride = 256 floats = 1024 B)
        si[s][hs] = make_int4((rb + cy0 * Wl + cx0) << 10, (rb + cy0 * Wl + cx1) << 10,
                              (rb + cy1 * Wl + cx0) << 10, (rb + cy1 * Wl + cx1) << 10);
        sw[s][hs] = make_float4(
            wa * (1.f - lx) * (1.f - ly) * (float)(vx0 && vy0),
            wa * lx         * (1.f - ly) * (float)(vx1 && vy0),
            wa * (1.f - lx) * ly         * (float)(vx0 && vy1),
            wa * lx         * ly         * (float)(vx1 && vy1));
    }
    __syncthreads();

    // ---- Phase 2: gather + accumulate (lane = 4 channels, float4) ----
    const int wid  = tid >> 5;
    const int lane = tid & 31;
    const int slot = wid * 4 + (lane >> 3);
    const int row  = rowBase + (slot >> 3);
    const int h    = slot & 7;
    const int c4   = (lane & 7) * 4;           // channel quad

    const char* __restrict__ vbase = (const char*)(g_value + h * 32 + c4);
    float a0 = 0.f, a1 = 0.f, a2 = 0.f, a3 = 0.f;
#pragma unroll 4
    for (int t = 0; t < 16; t++) {
        const float4 w  = sw[t][slot];
        const int4   id = si[t][slot];
        const float4 f0 = *(const float4*)(vbase + id.x);
        const float4 f1 = *(const float4*)(vbase + id.y);
        const float4 f2 = *(const float4*)(vbase + id.z);
        const float4 f3 = *(const float4*)(vbase + id.w);
        a0 += w.x * f0.x + w.y * f1.x + w.z * f2.x + w.w * f3.x;
        a1 += w.x * f0.y + w.y * f1.y + w.z * f2.y + w.w * f3.y;
        a2 += w.x * f0.z + w.y * f1.z + w.z * f2.z + w.w * f3.z;
        a3 += w.x * f0.w + w.y * f1.w + w.z * f2.w + w.w * f3.w;
    }
    *(float4*)(g_core + (size_t)row * 256 + h * 32 + c4) =
        make_float4(a0, a1, a2, a3);
}

// ---------------------------------------------------------------------------
extern "C" void kernel_launch(void* const* d_in, const int* in_sizes, int n_in,
                              void* d_out, int out_size)
{
    const float* query  = (const float*)d_in[0];
    const float* refp   = (const float*)d_in[1];
    const float* inpf   = (const float*)d_in[2];
    const float* W_val  = (const float*)d_in[5];
    const float* b_val  = (const float*)d_in[6];
    const float* W_off  = (const float*)d_in[7];
    const float* b_off  = (const float*)d_in[8];
    const float* W_attn = (const float*)d_in[9];
    const float* b_attn = (const float*)d_in[10];
    const float* W_out  = (const float*)d_in[11];
    const float* b_out  = (const float*)d_in[12];
    float* out = (float*)d_out;

    float *p_val, *p_oa, *p_core, *p_boa;
    cudaGetSymbolAddress((void**)&p_val,  g_value);
    cudaGetSymbolAddress((void**)&p_oa,   g_oa);
    cudaGetSymbolAddress((void**)&p_core, g_core);
    cudaGetSymbolAddress((void**)&p_boa,  g_boa);
    __nv_bfloat16 *wv_h, *wv_l, *woa_h, *woa_l, *wu_h, *wu_l;
    cudaGetSymbolAddress((void**)&wv_h,  g_wv_hi);  cudaGetSymbolAddress((void**)&wv_l,  g_wv_lo);
    cudaGetSymbolAddress((void**)&woa_h, g_woa_hi); cudaGetSymbolAddress((void**)&woa_l, g_woa_lo);
    cudaGetSymbolAddress((void**)&wu_h,  g_wu_hi);  cudaGetSymbolAddress((void**)&wu_l,  g_wu_lo);

    constexpr int SMEM = 98304;
    cudaFuncSetAttribute(gemm_mma<256>, cudaFuncAttributeMaxDynamicSharedMemorySize, SMEM);
    cudaFuncSetAttribute(gemm_mma<384>, cudaFuncAttributeMaxDynamicSharedMemorySize, SMEM);

    // Fused weight prep: 229376 elements = 896 blocks x 256
    prep_all<<<896, 256>>>(W_val, W_off, W_attn, W_out, b_off, b_attn);

    const int MT = MTOT / 128;  // 340
    gemm_mma<256><<<dim3(4, MT), 256, SMEM>>>(inpf,  wv_h,  wv_l,  b_val, p_val);
    gemm_mma<384><<<dim3(6, MT), 256, SMEM>>>(query, woa_h, woa_l, p_boa, p_oa);

    // 4 query rows per block
    msda_sample<<<MTOT / 4, 256>>>(refp);

    gemm_mma<256><<<dim3(4, MT), 256, SMEM>>>(p_core, wu_h, wu_l, b_out, out);
}

// round 8
// speedup vs baseline: 1.6421x; 1.6421x over previous
#include <cuda_runtime.h>
#include <cuda_bf16.h>
#include <cuda_fp16.h>
#include <cstdint>

// Problem constants (fixed by the dataset)
#define BB   8
#define LQ   5440
#define LIN  5440
#define DM   256
#define NH   8
#define MTOT (BB * LQ)   // 43520

// ---------------------------------------------------------------------------
// Scratch (device globals; allocation-free per harness rules)
// ---------------------------------------------------------------------------
__device__ __align__(16) float g_value[MTOT * DM];          // fp32 value
__device__ __align__(16) float g_oa  [MTOT * 384];          // off(256) + attn logits(128)
__device__ __align__(16) float g_core[MTOT * DM];

// Pre-split / pre-transposed weights, chunk-contiguous bf16 layout:
// element index = ((k>>6)*N + n)*64 + (k&63)   (64-wide K chunks)
__device__ __align__(16) __nv_bfloat16 g_wv_hi [DM * DM],  g_wv_lo [DM * DM];
__device__ __align__(16) __nv_bfloat16 g_woa_hi[DM * 384], g_woa_lo[DM * 384];
__device__ __align__(16) __nv_bfloat16 g_wu_hi [DM * DM],  g_wu_lo [DM * DM];
__device__ __align__(16) float g_boa[384];

// ---------------------------------------------------------------------------
// Helpers (base-target ISA only: ldmatrix / cp.async / mma.sync)
// ---------------------------------------------------------------------------
__device__ __forceinline__ uint32_t smem_u32(const void* p) {
    uint32_t a;
    asm("{ .reg .u64 t; cvta.to.shared.u64 t, %1; cvt.u32.u64 %0, t; }"
        : "=r"(a) : "l"(p));
    return a;
}
__device__ __forceinline__ void ldsm4(uint32_t* d, uint32_t addr) {
    asm volatile("ldmatrix.sync.aligned.m8n8.x4.shared.b16 {%0,%1,%2,%3}, [%4];"
                 : "=r"(d[0]), "=r"(d[1]), "=r"(d[2]), "=r"(d[3]) : "r"(addr));
}
__device__ __forceinline__ void mma16816(float* c, const uint32_t* a,
                                         const uint32_t* b) {
    asm volatile(
        "mma.sync.aligned.m16n8k16.row.col.f32.bf16.bf16.f32 "
        "{%0,%1,%2,%3}, {%4,%5,%6,%7}, {%8,%9}, {%0,%1,%2,%3};"
        : "+f"(c[0]), "+f"(c[1]), "+f"(c[2]), "+f"(c[3])
        : "r"(a[0]), "r"(a[1]), "r"(a[2]), "r"(a[3]), "r"(b[0]), "r"(b[1]));
}
__device__ __forceinline__ void cp16(uint32_t dst, const void* src) {
    asm volatile("cp.async.cg.shared.global [%0], [%1], 16;"
                 :: "r"(dst), "l"(src) : "memory");
}
__device__ __forceinline__ uint32_t sw128(uint32_t b) { return b ^ ((b >> 3) & 0x70); }

// ---------------------------------------------------------------------------
// Fused weight prep: all three weight matrices (val / off+attn combined / out)
// transposed + bf16 hi/lo split into chunk-contiguous layout, plus combined bias.
// ---------------------------------------------------------------------------
__global__ void prep_all(const float* __restrict__ W_val,
                         const float* __restrict__ W_off,
                         const float* __restrict__ W_attn,
                         const float* __restrict__ W_out,
                         const float* __restrict__ b_off,
                         const float* __restrict__ b_attn)
{
    __nv_bfloat16 *wv_h = g_wv_hi,  *wv_l = g_wv_lo;
    __nv_bfloat16 *wa_h = g_woa_hi, *wa_l = g_woa_lo;
    __nv_bfloat16 *wu_h = g_wu_hi,  *wu_l = g_wu_lo;

    int idx = blockIdx.x * 256 + threadIdx.x;
    if (idx < 384)
        g_boa[idx] = idx < 256 ? b_off[idx] : b_attn[idx - 256];

    float v; __nv_bfloat16 *hi, *lo; int o;
    if (idx < 65536) {                       // W_val [256x256]
        int k = idx >> 8, n = idx & 255;
        v = W_val[idx];
        o = (((k >> 6) << 8) + n) * 64 + (k & 63);
        hi = wv_h; lo = wv_l;
    } else if (idx < 65536 + 98304) {        // combined [256x384]
        int t = idx - 65536;
        int k = t / 384, n = t - k * 384;
        v = n < 256 ? W_off[k * 256 + n] : W_attn[k * 128 + (n - 256)];
        o = ((k >> 6) * 384 + n) * 64 + (k & 63);
        hi = wa_h; lo = wa_l;
    } else {                                 // W_out [256x256]
        int t = idx - 65536 - 98304;
        int k = t >> 8, n = t & 255;
        v = W_out[t];
        o = (((k >> 6) << 8) + n) * 64 + (k & 63);
        hi = wu_h; lo = wu_l;
    }
    __nv_bfloat16 h = __float2bfloat16(v);
    hi[o] = h;
    lo[o] = __float2bfloat16(v - __bfloat162float(h));
}

// ---------------------------------------------------------------------------
// mma.sync bf16 GEMM, 3-term split: C[M,N] = A[M,256]*W + bias (fp32-grade).
// CTA: 128x64 tile, 256 thr (8 warps; warp tile 32x32). K: 4 chunks of 64,
// double-buffered smem (48KB/buffer, 96KB total -> 2 CTAs/SM).
// ---------------------------------------------------------------------------
template <int N>
__global__ __launch_bounds__(256, 2) void gemm_mma(
    const float* __restrict__ A,
    const __nv_bfloat16* __restrict__ Bh_g, const __nv_bfloat16* __restrict__ Bl_g,
    const float* __restrict__ bias, float* __restrict__ C)
{
    extern __shared__ char smem[];
    constexpr int BUF = 49152;
    constexpr int O_AL = 16384, O_BH = 32768, O_BL = 40960;

    const int tid  = threadIdx.x;
    const int wid  = tid >> 5;
    const int lane = tid & 31;
    const int mBase = blockIdx.y * 128;
    const int nBase = blockIdx.x * 64;
    const int warpM = (wid & 3) * 32;
    const int warpN = (wid >> 2) * 32;

    const float4* Ag  = (const float4*)A;
    const uint4*  Bhg = (const uint4*)Bh_g;
    const uint4*  Blg = (const uint4*)Bl_g;

    float acc[2][4][4];
#pragma unroll
    for (int i = 0; i < 2; i++)
#pragma unroll
        for (int j = 0; j < 4; j++)
#pragma unroll
            for (int k = 0; k < 4; k++) acc[i][j][k] = 0.f;

    auto loadB = [&](int c, char* buf) {
        uint32_t bh = smem_u32(buf + O_BH), bl = smem_u32(buf + O_BL);
#pragma unroll
        for (int i = 0; i < 2; i++) {
            int f = tid + 256 * i;
            int n = f >> 3, u = f & 7;
            uint32_t so = (n << 7) + (((u ^ (n & 7))) << 4);
            size_t gi = (size_t)(c * N + nBase + n) * 8 + u;
            cp16(bh + so, Bhg + gi);
            cp16(bl + so, Blg + gi);
        }
        asm volatile("cp.async.commit_group;" ::: "memory");
    };

    float4 apf[8];
    auto loadA = [&](int c) {
#pragma unroll
        for (int i = 0; i < 8; i++) {
            int f = tid + 256 * i;
            int row = f >> 4, q = f & 15;
            apf[i] = Ag[(size_t)(mBase + row) * 64 + c * 16 + q];
        }
    };
    auto storeA = [&](char* buf) {
        char* ah = buf;
        char* al = buf + O_AL;
#pragma unroll
        for (int i = 0; i < 8; i++) {
            int f = tid + 256 * i;
            int row = f >> 4, q = f & 15;
            float4 v = apf[i];
            __nv_bfloat162 h0 = __floats2bfloat162_rn(v.x, v.y);
            __nv_bfloat162 h1 = __floats2bfloat162_rn(v.z, v.w);
            float2 f0 = __bfloat1622float2(h0), f1 = __bfloat1622float2(h1);
            __nv_bfloat162 l0 = __floats2bfloat162_rn(v.x - f0.x, v.y - f0.y);
            __nv_bfloat162 l1 = __floats2bfloat162_rn(v.z - f1.x, v.w - f1.y);
            uint32_t so = sw128(row * 128 + q * 8);
            *(__nv_bfloat162*)(ah + so)     = h0;
            *(__nv_bfloat162*)(ah + so + 4) = h1;
            *(__nv_bfloat162*)(al + so)     = l0;
            *(__nv_bfloat162*)(al + so + 4) = l1;
        }
    };

    loadB(0, smem);
    loadA(0);

    for (int c = 0; c < 4; c++) {
        char* buf = smem + (c & 1) * BUF;
        storeA(buf);
        if (c < 3) loadB(c + 1, smem + ((c + 1) & 1) * BUF);
        if (c < 3) asm volatile("cp.async.wait_group 1;" ::: "memory");
        else       asm volatile("cp.async.wait_group 0;" ::: "memory");
        __syncthreads();
        if (c < 3) loadA(c + 1);

        const uint32_t Ah = smem_u32(buf);
        const uint32_t Al = Ah + O_AL;
        const uint32_t Bh = Ah + O_BH;
        const uint32_t Bl = Ah + O_BL;

#pragma unroll
        for (int kk = 0; kk < 4; kk++) {
            uint32_t ah[2][4], al[2][4];
#pragma unroll
            for (int mi = 0; mi < 2; mi++) {
                int r = warpM + mi * 16 + (lane & 15);
                int u = kk * 2 + (lane >> 4);
                uint32_t off = (r << 7) + (((u ^ (r & 7))) << 4);
                ldsm4(ah[mi], Ah + off);
                ldsm4(al[mi], Al + off);
            }
            uint32_t bh[4][2], bl[4][2];
#pragma unroll
            for (int p = 0; p < 2; p++) {
                int r = warpN + p * 16 + ((lane >> 4) << 3) + (lane & 7);
                int u = kk * 2 + ((lane >> 3) & 1);
                uint32_t off = (r << 7) + (((u ^ (r & 7))) << 4);
                ldsm4(&bh[p * 2][0], Bh + off);
                ldsm4(&bl[p * 2][0], Bl + off);
            }
#pragma unroll
            for (int mi = 0; mi < 2; mi++)
#pragma unroll
                for (int j = 0; j < 4; j++) {
                    float* cc = acc[mi][j];
                    mma16816(cc, ah[mi], bh[j]);
                    mma16816(cc, ah[mi], bl[j]);
                    mma16816(cc, al[mi], bh[j]);
                }
        }
        __syncthreads();
    }

    // ---- epilogue: bias + store ----
#pragma unroll
    for (int mi = 0; mi < 2; mi++) {
        int row0 = mBase + warpM + mi * 16 + (lane >> 2);
#pragma unroll
        for (int nj = 0; nj < 4; nj++) {
            int col = nBase + warpN + nj * 8 + (lane & 3) * 2;
            float bx = __ldg(bias + col), by = __ldg(bias + col + 1);
            *(float2*)(C + (size_t)row0 * N + col) =
                make_float2(acc[mi][nj][0] + bx, acc[mi][nj][1] + by);
            *(float2*)(C + (size_t)(row0 + 8) * N + col) =
                make_float2(acc[mi][nj][2] + bx, acc[mi][nj][3] + by);
        }
    }
}

// ---------------------------------------------------------------------------
// Fused softmax + deformable sampling (R5 structure, fp32 value, float2 loads).
// Block = 256 threads = 2 query rows x 8 heads = 16 head-slots.
// Phase 1: thread (hs, s) computes softmax'd bilinear weights + gather
//          indices for one (head, point) -> smem float4/int4.
// Phase 2: warp w serves head-slots {2w, 2w+1}: 16 lanes per head, lane = 2
//          channels (float2). Inner loop per point: 2 broadcast LDS.128 +
//          4 LDG.64 + 8 FFMA. No shuffles, no converts.
// ---------------------------------------------------------------------------
__global__ __launch_bounds__(256) void msda_sample(const float* __restrict__ refp)
{
    __shared__ float4 sw[16][16];
    __shared__ int4   si[16][16];

    const int tid = threadIdx.x;
    const int rowBase = blockIdx.x * 2;

    // ---- Phase 1: per-(head,point) setup ----
    {
        const int hs  = tid >> 4;        // head slot 0..15
        const int s   = tid & 15;        // point (lvl*4 + pt)
        const int row = rowBase + (hs >> 3);
        const int h   = hs & 7;
        const int b   = row / LQ;

        const int lvl = s >> 2;
        const int Wl  = 64 >> lvl;
        const int st  = (16384 - (16384 >> (2 * lvl))) / 3;

        const float refx = refp[row * 8 + lvl * 2 + 0];
        const float refy = refp[row * 8 + lvl * 2 + 1];
        const int obase  = row * 384 + ((h * 16 + s) * 2);
        const float offx = g_oa[obase + 0];
        const float offy = g_oa[obase + 1];

        const float x = refx * (float)Wl + offx - 0.5f;
        const float y = refy * (float)Wl + offy - 0.5f;
        const float fx = floorf(x), fy = floorf(y);
        const float lx = x - fx,   ly = y - fy;
        const int x0 = (int)fx, y0 = (int)fy;
        const int x1 = x0 + 1,  y1 = y0 + 1;

        const float logit = g_oa[row * 384 + 256 + h * 16 + s];
        float mx = logit;
#pragma unroll
        for (int o = 8; o; o >>= 1) mx = fmaxf(mx, __shfl_xor_sync(~0u, mx, o, 16));
        const float e = __expf(logit - mx);
        float sum = e;
#pragma unroll
        for (int o = 8; o; o >>= 1) sum += __shfl_xor_sync(~0u, sum, o, 16);
        const float wa = e / sum;

        const bool vx0 = (unsigned)x0 < (unsigned)Wl;
        const bool vx1 = (unsigned)x1 < (unsigned)Wl;
        const bool vy0 = (unsigned)y0 < (unsigned)Wl;
        const bool vy1 = (unsigned)y1 < (unsigned)Wl;
        const int cx0 = min(max(x0, 0), Wl - 1);
        const int cx1 = min(max(x1, 0), Wl - 1);
        const int cy0 = min(max(y0, 0), Wl - 1);
        const int cy1 = min(max(y1, 0), Wl - 1);
        const int rb  = b * LIN + st;

        si[hs][s] = make_int4(rb + cy0 * Wl + cx0, rb + cy0 * Wl + cx1,
                              rb + cy1 * Wl + cx0, rb + cy1 * Wl + cx1);
        sw[hs][s] = make_float4(
            wa * (1.f - lx) * (1.f - ly) * (float)(vx0 && vy0),
            wa * lx         * (1.f - ly) * (float)(vx1 && vy0),
            wa * (1.f - lx) * ly         * (float)(vx0 && vy1),
            wa * lx         * ly         * (float)(vx1 && vy1));
    }
    __syncthreads();

    // ---- Phase 2: gather + accumulate ----
    const int wid  = tid >> 5;
    const int lane = tid & 31;
    const int hs   = wid * 2 + (lane >> 4);
    const int row  = rowBase + (hs >> 3);
    const int h    = hs & 7;
    const int c2   = (lane & 15) * 2;          // channel pair

    const float* __restrict__ vp = g_value + h * 32 + c2;
    float ax = 0.f, ay = 0.f;
#pragma unroll 4
    for (int t = 0; t < 16; t++) {
        const float4 w  = sw[hs][t];
        const int4   id = si[hs][t];
        const float2 f0 = *(const float2*)(vp + (size_t)id.x * 256);
        const float2 f1 = *(const float2*)(vp + (size_t)id.y * 256);
        const float2 f2 = *(const float2*)(vp + (size_t)id.z * 256);
        const float2 f3 = *(const float2*)(vp + (size_t)id.w * 256);
        ax += w.x * f0.x + w.y * f1.x + w.z * f2.x + w.w * f3.x;
        ay += w.x * f0.y + w.y * f1.y + w.z * f2.y + w.w * f3.y;
    }
    *(float2*)(g_core + (size_t)row * 256 + h * 32 + c2) = make_float2(ax, ay);
}

// ---------------------------------------------------------------------------
extern "C" void kernel_launch(void* const* d_in, const int* in_sizes, int n_in,
                              void* d_out, int out_size)
{
    const float* query  = (const float*)d_in[0];
    const float* refp   = (const float*)d_in[1];
    const float* inpf   = (const float*)d_in[2];
    const float* W_val  = (const float*)d_in[5];
    const float* b_val  = (const float*)d_in[6];
    const float* W_off  = (const float*)d_in[7];
    const float* b_off  = (const float*)d_in[8];
    const float* W_attn = (const float*)d_in[9];
    const float* b_attn = (const float*)d_in[10];
    const float* W_out  = (const float*)d_in[11];
    const float* b_out  = (const float*)d_in[12];
    float* out = (float*)d_out;

    float *p_val, *p_oa, *p_core, *p_boa;
    cudaGetSymbolAddress((void**)&p_val,  g_value);
    cudaGetSymbolAddress((void**)&p_oa,   g_oa);
    cudaGetSymbolAddress((void**)&p_core, g_core);
    cudaGetSymbolAddress((void**)&p_boa,  g_boa);
    __nv_bfloat16 *wv_h, *wv_l, *woa_h, *woa_l, *wu_h, *wu_l;
    cudaGetSymbolAddress((void**)&wv_h,  g_wv_hi);  cudaGetSymbolAddress((void**)&wv_l,  g_wv_lo);
    cudaGetSymbolAddress((void**)&woa_h, g_woa_hi); cudaGetSymbolAddress((void**)&woa_l, g_woa_lo);
    cudaGetSymbolAddress((void**)&wu_h,  g_wu_hi);  cudaGetSymbolAddress((void**)&wu_l,  g_wu_lo);

    constexpr int SMEM = 98304;
    cudaFuncSetAttribute(gemm_mma<256>, cudaFuncAttributeMaxDynamicSharedMemorySize, SMEM);
    cudaFuncSetAttribute(gemm_mma<384>, cudaFuncAttributeMaxDynamicSharedMemorySize, SMEM);

    // Fused weight prep: 229376 elements = 896 blocks x 256
    prep_all<<<896, 256>>>(W_val, W_off, W_attn, W_out, b_off, b_attn);

    const int MT = MTOT / 128;  // 340
    gemm_mma<256><<<dim3(4, MT), 256, SMEM>>>(inpf,  wv_h,  wv_l,  b_val, p_val);
    gemm_mma<384><<<dim3(6, MT), 256, SMEM>>>(query, woa_h, woa_l, p_boa, p_oa);

    // 2 query rows per block
    msda_sample<<<MTOT / 2, 256>>>(refp);

    gemm_mma<256><<<dim3(4, MT), 256, SMEM>>>(p_core, wu_h, wu_l, b_out, out);
}

// round 9
// speedup vs baseline: 1.8169x; 1.1065x over previous
#include <cuda_runtime.h>
#include <cuda_bf16.h>
#include <cuda_fp16.h>
#include <cstdint>

// Problem constants (fixed by the dataset)
#define BB   8
#define LQ   5440
#define LIN  5440
#define DM   256
#define NH   8
#define MTOT (BB * LQ)   // 43520

// ---------------------------------------------------------------------------
// Scratch (device globals; allocation-free per harness rules)
// ---------------------------------------------------------------------------
__device__ __align__(16) __half g_value_h[MTOT * DM];       // fp16 value
__device__ __align__(16) float  g_oa  [MTOT * 384];         // off(256) + attn logits(128)
// core in bf16 hi/lo, chunk-contiguous GEMM layout:
// half index = ((k>>6)*MTOT + row)*64 + (k&63),  k = h*32 + ch
__device__ __align__(16) __nv_bfloat16 g_core_hi[MTOT * DM];
__device__ __align__(16) __nv_bfloat16 g_core_lo[MTOT * DM];

// Pre-split / pre-transposed weights, chunk-contiguous bf16 layout:
// element index = ((k>>6)*N + n)*64 + (k&63)   (64-wide K chunks)
__device__ __align__(16) __nv_bfloat16 g_wv_hi [DM * DM],  g_wv_lo [DM * DM];
__device__ __align__(16) __nv_bfloat16 g_woa_hi[DM * 384], g_woa_lo[DM * 384];
__device__ __align__(16) __nv_bfloat16 g_wu_hi [DM * DM],  g_wu_lo [DM * DM];
__device__ __align__(16) float g_boa[384];

// ---------------------------------------------------------------------------
// Helpers (base-target ISA only: ldmatrix / cp.async / mma.sync)
// ---------------------------------------------------------------------------
__device__ __forceinline__ uint32_t smem_u32(const void* p) {
    uint32_t a;
    asm("{ .reg .u64 t; cvta.to.shared.u64 t, %1; cvt.u32.u64 %0, t; }"
        : "=r"(a) : "l"(p));
    return a;
}
__device__ __forceinline__ void ldsm4(uint32_t* d, uint32_t addr) {
    asm volatile("ldmatrix.sync.aligned.m8n8.x4.shared.b16 {%0,%1,%2,%3}, [%4];"
                 : "=r"(d[0]), "=r"(d[1]), "=r"(d[2]), "=r"(d[3]) : "r"(addr));
}
__device__ __forceinline__ void mma16816(float* c, const uint32_t* a,
                                         const uint32_t* b) {
    asm volatile(
        "mma.sync.aligned.m16n8k16.row.col.f32.bf16.bf16.f32 "
        "{%0,%1,%2,%3}, {%4,%5,%6,%7}, {%8,%9}, {%0,%1,%2,%3};"
        : "+f"(c[0]), "+f"(c[1]), "+f"(c[2]), "+f"(c[3])
        : "r"(a[0]), "r"(a[1]), "r"(a[2]), "r"(a[3]), "r"(b[0]), "r"(b[1]));
}
__device__ __forceinline__ void cp16(uint32_t dst, const void* src) {
    asm volatile("cp.async.cg.shared.global [%0], [%1], 16;"
                 :: "r"(dst), "l"(src) : "memory");
}
__device__ __forceinline__ uint32_t sw128(uint32_t b) { return b ^ ((b >> 3) & 0x70); }

// ---------------------------------------------------------------------------
// Fused weight prep
// ---------------------------------------------------------------------------
__global__ void prep_all(const float* __restrict__ W_val,
                         const float* __restrict__ W_off,
                         const float* __restrict__ W_attn,
                         const float* __restrict__ W_out,
                         const float* __restrict__ b_off,
                         const float* __restrict__ b_attn)
{
    int idx = blockIdx.x * 256 + threadIdx.x;
    if (idx < 384)
        g_boa[idx] = idx < 256 ? b_off[idx] : b_attn[idx - 256];

    float v; __nv_bfloat16 *hi, *lo; int o;
    if (idx < 65536) {                       // W_val [256x256]
        int k = idx >> 8, n = idx & 255;
        v = W_val[idx];
        o = (((k >> 6) << 8) + n) * 64 + (k & 63);
        hi = g_wv_hi; lo = g_wv_lo;
    } else if (idx < 65536 + 98304) {        // combined [256x384]
        int t = idx - 65536;
        int k = t / 384, n = t - k * 384;
        v = n < 256 ? W_off[k * 256 + n] : W_attn[k * 128 + (n - 256)];
        o = ((k >> 6) * 384 + n) * 64 + (k & 63);
        hi = g_woa_hi; lo = g_woa_lo;
    } else {                                 // W_out [256x256]
        int t = idx - 65536 - 98304;
        int k = t >> 8, n = t & 255;
        v = W_out[t];
        o = (((k >> 6) << 8) + n) * 64 + (k & 63);
        hi = g_wu_hi; lo = g_wu_lo;
    }
    __nv_bfloat16 h = __float2bfloat16(v);
    hi[o] = h;
    lo[o] = __float2bfloat16(v - __bfloat162float(h));
}

// ---------------------------------------------------------------------------
// mma.sync bf16 GEMM, 3-term split, A fp32 converted in-kernel.
// CTA 128x64, 256 thr, warp tile 32x32, K 4x64 double-buffered (2 CTA/SM).
// ---------------------------------------------------------------------------
template <int N, typename OutT>
__global__ __launch_bounds__(256, 2) void gemm_mma(
    const float* __restrict__ A,
    const __nv_bfloat16* __restrict__ Bh_g, const __nv_bfloat16* __restrict__ Bl_g,
    const float* __restrict__ bias, OutT* __restrict__ C)
{
    extern __shared__ char smem[];
    constexpr int BUF = 49152;
    constexpr int O_AL = 16384, O_BH = 32768, O_BL = 40960;

    const int tid  = threadIdx.x;
    const int wid  = tid >> 5;
    const int lane = tid & 31;
    const int mBase = blockIdx.y * 128;
    const int nBase = blockIdx.x * 64;
    const int warpM = (wid & 3) * 32;
    const int warpN = (wid >> 2) * 32;

    const float4* Ag  = (const float4*)A;
    const uint4*  Bhg = (const uint4*)Bh_g;
    const uint4*  Blg = (const uint4*)Bl_g;

    float acc[2][4][4];
#pragma unroll
    for (int i = 0; i < 2; i++)
#pragma unroll
        for (int j = 0; j < 4; j++)
#pragma unroll
            for (int k = 0; k < 4; k++) acc[i][j][k] = 0.f;

    auto loadB = [&](int c, char* buf) {
        uint32_t bh = smem_u32(buf + O_BH), bl = smem_u32(buf + O_BL);
#pragma unroll
        for (int i = 0; i < 2; i++) {
            int f = tid + 256 * i;
            int n = f >> 3, u = f & 7;
            uint32_t so = (n << 7) + (((u ^ (n & 7))) << 4);
            size_t gi = (size_t)(c * N + nBase + n) * 8 + u;
            cp16(bh + so, Bhg + gi);
            cp16(bl + so, Blg + gi);
        }
        asm volatile("cp.async.commit_group;" ::: "memory");
    };

    float4 apf[8];
    auto loadA = [&](int c) {
#pragma unroll
        for (int i = 0; i < 8; i++) {
            int f = tid + 256 * i;
            int row = f >> 4, q = f & 15;
            apf[i] = Ag[(size_t)(mBase + row) * 64 + c * 16 + q];
        }
    };
    auto storeA = [&](char* buf) {
        char* ah = buf;
        char* al = buf + O_AL;
#pragma unroll
        for (int i = 0; i < 8; i++) {
            int f = tid + 256 * i;
            int row = f >> 4, q = f & 15;
            float4 v = apf[i];
            __nv_bfloat162 h0 = __floats2bfloat162_rn(v.x, v.y);
            __nv_bfloat162 h1 = __floats2bfloat162_rn(v.z, v.w);
            float2 f0 = __bfloat1622float2(h0), f1 = __bfloat1622float2(h1);
            __nv_bfloat162 l0 = __floats2bfloat162_rn(v.x - f0.x, v.y - f0.y);
            __nv_bfloat162 l1 = __floats2bfloat162_rn(v.z - f1.x, v.w - f1.y);
            uint32_t so = sw128(row * 128 + q * 8);
            *(__nv_bfloat162*)(ah + so)     = h0;
            *(__nv_bfloat162*)(ah + so + 4) = h1;
            *(__nv_bfloat162*)(al + so)     = l0;
            *(__nv_bfloat162*)(al + so + 4) = l1;
        }
    };

    loadB(0, smem);
    loadA(0);

    for (int c = 0; c < 4; c++) {
        char* buf = smem + (c & 1) * BUF;
        storeA(buf);
        if (c < 3) loadB(c + 1, smem + ((c + 1) & 1) * BUF);
        if (c < 3) asm volatile("cp.async.wait_group 1;" ::: "memory");
        else       asm volatile("cp.async.wait_group 0;" ::: "memory");
        __syncthreads();
        if (c < 3) loadA(c + 1);

        const uint32_t Ah = smem_u32(buf);
        const uint32_t Al = Ah + O_AL;
        const uint32_t Bh = Ah + O_BH;
        const uint32_t Bl = Ah + O_BL;

#pragma unroll
        for (int kk = 0; kk < 4; kk++) {
            uint32_t ah[2][4], al[2][4];
#pragma unroll
            for (int mi = 0; mi < 2; mi++) {
                int r = warpM + mi * 16 + (lane & 15);
                int u = kk * 2 + (lane >> 4);
                uint32_t off = (r << 7) + (((u ^ (r & 7))) << 4);
                ldsm4(ah[mi], Ah + off);
                ldsm4(al[mi], Al + off);
            }
            uint32_t bh[4][2], bl[4][2];
#pragma unroll
            for (int p = 0; p < 2; p++) {
                int r = warpN + p * 16 + ((lane >> 4) << 3) + (lane & 7);
                int u = kk * 2 + ((lane >> 3) & 1);
                uint32_t off = (r << 7) + (((u ^ (r & 7))) << 4);
                ldsm4(&bh[p * 2][0], Bh + off);
                ldsm4(&bl[p * 2][0], Bl + off);
            }
#pragma unroll
            for (int mi = 0; mi < 2; mi++)
#pragma unroll
                for (int j = 0; j < 4; j++) {
                    float* cc = acc[mi][j];
                    mma16816(cc, ah[mi], bh[j]);
                    mma16816(cc, ah[mi], bl[j]);
                    mma16816(cc, al[mi], bh[j]);
                }
        }
        __syncthreads();
    }

#pragma unroll
    for (int mi = 0; mi < 2; mi++) {
        int row0 = mBase + warpM + mi * 16 + (lane >> 2);
#pragma unroll
        for (int nj = 0; nj < 4; nj++) {
            int col = nBase + warpN + nj * 8 + (lane & 3) * 2;
            float bx = __ldg(bias + col), by = __ldg(bias + col + 1);
            float v00 = acc[mi][nj][0] + bx, v01 = acc[mi][nj][1] + by;
            float v10 = acc[mi][nj][2] + bx, v11 = acc[mi][nj][3] + by;
            if constexpr (sizeof(OutT) == 4) {
                *(float2*)((float*)C + (size_t)row0 * N + col)       = make_float2(v00, v01);
                *(float2*)((float*)C + (size_t)(row0 + 8) * N + col) = make_float2(v10, v11);
            } else {
                *(__half2*)((__half*)C + (size_t)row0 * N + col)       = __floats2half2_rn(v00, v01);
                *(__half2*)((__half*)C + (size_t)(row0 + 8) * N + col) = __floats2half2_rn(v10, v11);
            }
        }
    }
}

// ---------------------------------------------------------------------------
// Output GEMM: A pre-split bf16 hi/lo (chunk layout) -> pure cp.async pipeline.
// ---------------------------------------------------------------------------
__global__ __launch_bounds__(256, 2) void gemm_pre(
    const __nv_bfloat16* __restrict__ Ah_g, const __nv_bfloat16* __restrict__ Al_g,
    const __nv_bfloat16* __restrict__ Bh_g, const __nv_bfloat16* __restrict__ Bl_g,
    const float* __restrict__ bias, float* __restrict__ C)
{
    extern __shared__ char smem[];
    constexpr int BUF = 49152;
    constexpr int O_AL = 16384, O_BH = 32768, O_BL = 40960;
    constexpr int N = 256;

    const int tid  = threadIdx.x;
    const int wid  = tid >> 5;
    const int lane = tid & 31;
    const int mBase = blockIdx.y * 128;
    const int nBase = blockIdx.x * 64;
    const int warpM = (wid & 3) * 32;
    const int warpN = (wid >> 2) * 32;

    const uint4* Ahg = (const uint4*)Ah_g;
    const uint4* Alg = (const uint4*)Al_g;
    const uint4* Bhg = (const uint4*)Bh_g;
    const uint4* Blg = (const uint4*)Bl_g;

    float acc[2][4][4];
#pragma unroll
    for (int i = 0; i < 2; i++)
#pragma unroll
        for (int j = 0; j < 4; j++)
#pragma unroll
            for (int k = 0; k < 4; k++) acc[i][j][k] = 0.f;

    auto loadChunk = [&](int c, char* buf) {
        uint32_t ah = smem_u32(buf), al = ah + O_AL;
        uint32_t bh = ah + O_BH,     bl = ah + O_BL;
#pragma unroll
        for (int i = 0; i < 4; i++) {           // A: 1024 uint4 per split
            int f = tid + 256 * i;
            int row = f >> 3, u = f & 7;
            uint32_t so = (row << 7) + (((u ^ (row & 7))) << 4);
            size_t gi = (size_t)(c * MTOT + mBase + row) * 8 + u;
            cp16(ah + so, Ahg + gi);
            cp16(al + so, Alg + gi);
        }
#pragma unroll
        for (int i = 0; i < 2; i++) {           // B: 512 uint4 per split
            int f = tid + 256 * i;
            int n = f >> 3, u = f & 7;
            uint32_t so = (n << 7) + (((u ^ (n & 7))) << 4);
            size_t gi = (size_t)(c * N + nBase + n) * 8 + u;
            cp16(bh + so, Bhg + gi);
            cp16(bl + so, Blg + gi);
        }
        asm volatile("cp.async.commit_group;" ::: "memory");
    };

    loadChunk(0, smem);

    for (int c = 0; c < 4; c++) {
        char* buf = smem + (c & 1) * BUF;
        if (c < 3) loadChunk(c + 1, smem + ((c + 1) & 1) * BUF);
        if (c < 3) asm volatile("cp.async.wait_group 1;" ::: "memory");
        else       asm volatile("cp.async.wait_group 0;" ::: "memory");
        __syncthreads();

        const uint32_t Ah = smem_u32(buf);
        const uint32_t Al = Ah + O_AL;
        const uint32_t Bh = Ah + O_BH;
        const uint32_t Bl = Ah + O_BL;

#pragma unroll
        for (int kk = 0; kk < 4; kk++) {
            uint32_t ah[2][4], al[2][4];
#pragma unroll
            for (int mi = 0; mi < 2; mi++) {
                int r = warpM + mi * 16 + (lane & 15);
                int u = kk * 2 + (lane >> 4);
                uint32_t off = (r << 7) + (((u ^ (r & 7))) << 4);
                ldsm4(ah[mi], Ah + off);
                ldsm4(al[mi], Al + off);
            }
            uint32_t bh[4][2], bl[4][2];
#pragma unroll
            for (int p = 0; p < 2; p++) {
                int r = warpN + p * 16 + ((lane >> 4) << 3) + (lane & 7);
                int u = kk * 2 + ((lane >> 3) & 1);
                uint32_t off = (r << 7) + (((u ^ (r & 7))) << 4);
                ldsm4(&bh[p * 2][0], Bh + off);
                ldsm4(&bl[p * 2][0], Bl + off);
            }
#pragma unroll
            for (int mi = 0; mi < 2; mi++)
#pragma unroll
                for (int j = 0; j < 4; j++) {
                    float* cc = acc[mi][j];
                    mma16816(cc, ah[mi], bh[j]);
                    mma16816(cc, ah[mi], bl[j]);
                    mma16816(cc, al[mi], bh[j]);
                }
        }
        __syncthreads();
    }

#pragma unroll
    for (int mi = 0; mi < 2; mi++) {
        int row0 = mBase + warpM + mi * 16 + (lane >> 2);
#pragma unroll
        for (int nj = 0; nj < 4; nj++) {
            int col = nBase + warpN + nj * 8 + (lane & 3) * 2;
            float bx = __ldg(bias + col), by = __ldg(bias + col + 1);
            *(float2*)(C + (size_t)row0 * N + col) =
                make_float2(acc[mi][nj][0] + bx, acc[mi][nj][1] + by);
            *(float2*)(C + (size_t)(row0 + 8) * N + col) =
                make_float2(acc[mi][nj][2] + bx, acc[mi][nj][3] + by);
        }
    }
}

// ---------------------------------------------------------------------------
// Fused softmax + deformable sampling (R5 structure + padded smem tables).
// Block = 256 threads = 2 query rows x 8 heads = 16 head-slots.
// Phase 2: warp serves 2 head-slots, 16 lanes per slot, lane = 2 channels
// (half2). Tables padded to stride 17 -> the two half-warp broadcasts land
// on disjoint banks (no 2-way LDS conflict).
// Output written as bf16 hi/lo in the out-GEMM chunk layout.
// ---------------------------------------------------------------------------
__global__ __launch_bounds__(256) void msda_sample(const float* __restrict__ refp)
{
    __shared__ float4 sw[16][17];
    __shared__ int4   si[16][17];

    const int tid = threadIdx.x;
    const int rowBase = blockIdx.x * 2;

    // ---- Phase 1: per-(head,point) setup ----
    {
        const int hs  = tid >> 4;        // head slot 0..15
        const int s   = tid & 15;        // point (lvl*4 + pt)
        const int row = rowBase + (hs >> 3);
        const int h   = hs & 7;
        const int b   = row / LQ;

        const int lvl = s >> 2;
        const int Wl  = 64 >> lvl;
        const int st  = (16384 - (16384 >> (2 * lvl))) / 3;

        const float refx = refp[row * 8 + lvl * 2 + 0];
        const float refy = refp[row * 8 + lvl * 2 + 1];
        const int obase  = row * 384 + ((h * 16 + s) * 2);
        const float offx = g_oa[obase + 0];
        const float offy = g_oa[obase + 1];

        const float x = refx * (float)Wl + offx - 0.5f;
        const float y = refy * (float)Wl + offy - 0.5f;
        const float fx = floorf(x), fy = floorf(y);
        const float lx = x - fx,   ly = y - fy;
        const int x0 = (int)fx, y0 = (int)fy;
        const int x1 = x0 + 1,  y1 = y0 + 1;

        const float logit = g_oa[row * 384 + 256 + h * 16 + s];
        float mx = logit;
#pragma unroll
        for (int o = 8; o; o >>= 1) mx = fmaxf(mx, __shfl_xor_sync(~0u, mx, o, 16));
        const float e = __expf(logit - mx);
        float sum = e;
#pragma unroll
        for (int o = 8; o; o >>= 1) sum += __shfl_xor_sync(~0u, sum, o, 16);
        const float wa = e / sum;

        const bool vx0 = (unsigned)x0 < (unsigned)Wl;
        const bool vx1 = (unsigned)x1 < (unsigned)Wl;
        const bool vy0 = (unsigned)y0 < (unsigned)Wl;
        const bool vy1 = (unsigned)y1 < (unsigned)Wl;
        const int cx0 = min(max(x0, 0), Wl - 1);
        const int cx1 = min(max(x1, 0), Wl - 1);
        const int cy0 = min(max(y0, 0), Wl - 1);
        const int cy1 = min(max(y1, 0), Wl - 1);
        const int rb  = b * LIN + st;

        si[hs][s] = make_int4(rb + cy0 * Wl + cx0, rb + cy0 * Wl + cx1,
                              rb + cy1 * Wl + cx0, rb + cy1 * Wl + cx1);
        sw[hs][s] = make_float4(
            wa * (1.f - lx) * (1.f - ly) * (float)(vx0 && vy0),
            wa * lx         * (1.f - ly) * (float)(vx1 && vy0),
            wa * (1.f - lx) * ly         * (float)(vx0 && vy1),
            wa * lx         * ly         * (float)(vx1 && vy1));
    }
    __syncthreads();

    // ---- Phase 2: gather + accumulate ----
    const int wid  = tid >> 5;
    const int lane = tid & 31;
    const int hs   = wid * 2 + (lane >> 4);
    const int row  = rowBase + (hs >> 3);
    const int h    = hs & 7;
    const int c2   = (lane & 15) * 2;          // channel pair

    const __half* __restrict__ vp = g_value_h + h * 32 + c2;
    float ax = 0.f, ay = 0.f;
#pragma unroll 4
    for (int t = 0; t < 16; t++) {
        const float4 w  = sw[hs][t];
        const int4   id = si[hs][t];
        const float2 f0 = __half22float2(*(const __half2*)(vp + (size_t)id.x * 256));
        const float2 f1 = __half22float2(*(const __half2*)(vp + (size_t)id.y * 256));
        const float2 f2 = __half22float2(*(const __half2*)(vp + (size_t)id.z * 256));
        const float2 f3 = __half22float2(*(const __half2*)(vp + (size_t)id.w * 256));
        ax += w.x * f0.x + w.y * f1.x + w.z * f2.x + w.w * f3.x;
        ay += w.x * f0.y + w.y * f1.y + w.z * f2.y + w.w * f3.y;
    }

    // bf16 hi/lo split into out-GEMM chunk layout (k = h*32 + c2)
    __nv_bfloat162 hi2 = __floats2bfloat162_rn(ax, ay);
    float2 hf = __bfloat1622float2(hi2);
    __nv_bfloat162 lo2 = __floats2bfloat162_rn(ax - hf.x, ay - hf.y);
    size_t o = ((size_t)(h >> 1) * MTOT + row) * 64 + (h & 1) * 32 + c2;
    *(__nv_bfloat162*)(g_core_hi + o) = hi2;
    *(__nv_bfloat162*)(g_core_lo + o) = lo2;
}

// ---------------------------------------------------------------------------
extern "C" void kernel_launch(void* const* d_in, const int* in_sizes, int n_in,
                              void* d_out, int out_size)
{
    const float* query  = (const float*)d_in[0];
    const float* refp   = (const float*)d_in[1];
    const float* inpf   = (const float*)d_in[2];
    const float* W_val  = (const float*)d_in[5];
    const float* b_val  = (const float*)d_in[6];
    const float* W_off  = (const float*)d_in[7];
    const float* b_off  = (const float*)d_in[8];
    const float* W_attn = (const float*)d_in[9];
    const float* b_attn = (const float*)d_in[10];
    const float* W_out  = (const float*)d_in[11];
    const float* b_out  = (const float*)d_in[12];
    float* out = (float*)d_out;

    __half* p_val;  float *p_oa, *p_boa;
    __nv_bfloat16 *p_ch, *p_cl;
    cudaGetSymbolAddress((void**)&p_val, g_value_h);
    cudaGetSymbolAddress((void**)&p_oa,  g_oa);
    cudaGetSymbolAddress((void**)&p_boa, g_boa);
    cudaGetSymbolAddress((void**)&p_ch,  g_core_hi);
    cudaGetSymbolAddress((void**)&p_cl,  g_core_lo);
    __nv_bfloat16 *wv_h, *wv_l, *woa_h, *woa_l, *wu_h, *wu_l;
    cudaGetSymbolAddress((void**)&wv_h,  g_wv_hi);  cudaGetSymbolAddress((void**)&wv_l,  g_wv_lo);
    cudaGetSymbolAddress((void**)&woa_h, g_woa_hi); cudaGetSymbolAddress((void**)&woa_l, g_woa_lo);
    cudaGetSymbolAddress((void**)&wu_h,  g_wu_hi);  cudaGetSymbolAddress((void**)&wu_l,  g_wu_lo);

    constexpr int SMEM = 98304;
    cudaFuncSetAttribute(gemm_mma<256, __half>, cudaFuncAttributeMaxDynamicSharedMemorySize, SMEM);
    cudaFuncSetAttribute(gemm_mma<384, float>,  cudaFuncAttributeMaxDynamicSharedMemorySize, SMEM);
    cudaFuncSetAttribute(gemm_pre,              cudaFuncAttributeMaxDynamicSharedMemorySize, SMEM);

    prep_all<<<896, 256>>>(W_val, W_off, W_attn, W_out, b_off, b_attn);

    const int MT = MTOT / 128;  // 340
    gemm_mma<256, __half><<<dim3(4, MT), 256, SMEM>>>(inpf,  wv_h,  wv_l,  b_val, p_val);
    gemm_mma<384, float ><<<dim3(6, MT), 256, SMEM>>>(query, woa_h, woa_l, p_boa, p_oa);

    msda_sample<<<MTOT / 2, 256>>>(refp);

    gemm_pre<<<dim3(4, MT), 256, SMEM>>>(p_ch, p_cl, wu_h, wu_l, b_out, out);
}

// round 10
// speedup vs baseline: 2.1857x; 1.2030x over previous
#include <cuda_runtime.h>
#include <cuda_bf16.h>
#include <cuda_fp16.h>
#include <cstdint>

// Problem constants (fixed by the dataset)
#define BB   8
#define LQ   5440
#define LIN  5440
#define DM   256
#define NH   8
#define MTOT (BB * LQ)   // 43520

// ---------------------------------------------------------------------------
// Scratch (device globals; allocation-free per harness rules)
// ---------------------------------------------------------------------------
__device__ __align__(16) __half g_value_h[MTOT * DM];       // fp16 value
__device__ __align__(16) float  g_oa  [MTOT * 384];         // off(256) + attn logits(128)
// core as single fp16, chunk-contiguous GEMM layout:
// half index = ((k>>6)*MTOT + row)*64 + (k&63),  k = h*32 + ch
__device__ __align__(16) __half g_core_h[MTOT * DM];

// Pre-split / pre-transposed weights, fp16 hi/lo, chunk-contiguous layout:
// element index = ((k>>6)*N + n)*64 + (k&63)   (64-wide K chunks)
__device__ __align__(16) __half g_wv_hi [DM * DM],  g_wv_lo [DM * DM];
__device__ __align__(16) __half g_woa_hi[DM * 384], g_woa_lo[DM * 384];
__device__ __align__(16) __half g_wu_hi [DM * DM],  g_wu_lo [DM * DM];
__device__ __align__(16) float g_boa[384];

// ---------------------------------------------------------------------------
// Helpers (base-target ISA only: ldmatrix / cp.async / mma.sync)
// ---------------------------------------------------------------------------
__device__ __forceinline__ uint32_t smem_u32(const void* p) {
    uint32_t a;
    asm("{ .reg .u64 t; cvta.to.shared.u64 t, %1; cvt.u32.u64 %0, t; }"
        : "=r"(a) : "l"(p));
    return a;
}
__device__ __forceinline__ void ldsm4(uint32_t* d, uint32_t addr) {
    asm volatile("ldmatrix.sync.aligned.m8n8.x4.shared.b16 {%0,%1,%2,%3}, [%4];"
                 : "=r"(d[0]), "=r"(d[1]), "=r"(d[2]), "=r"(d[3]) : "r"(addr));
}
__device__ __forceinline__ void mma16816(float* c, const uint32_t* a,
                                         const uint32_t* b) {
    asm volatile(
        "mma.sync.aligned.m16n8k16.row.col.f32.f16.f16.f32 "
        "{%0,%1,%2,%3}, {%4,%5,%6,%7}, {%8,%9}, {%0,%1,%2,%3};"
        : "+f"(c[0]), "+f"(c[1]), "+f"(c[2]), "+f"(c[3])
        : "r"(a[0]), "r"(a[1]), "r"(a[2]), "r"(a[3]), "r"(b[0]), "r"(b[1]));
}
__device__ __forceinline__ void cp16(uint32_t dst, const void* src) {
    asm volatile("cp.async.cg.shared.global [%0], [%1], 16;"
                 :: "r"(dst), "l"(src) : "memory");
}
__device__ __forceinline__ uint32_t sw128(uint32_t b) { return b ^ ((b >> 3) & 0x70); }

// ---------------------------------------------------------------------------
// Fused weight prep: W (val / off+attn combined / out) transposed + fp16
// hi/lo split into chunk-contiguous layout, plus combined bias.
// ---------------------------------------------------------------------------
__global__ void prep_all(const float* __restrict__ W_val,
                         const float* __restrict__ W_off,
                         const float* __restrict__ W_attn,
                         const float* __restrict__ W_out,
                         const float* __restrict__ b_off,
                         const float* __restrict__ b_attn)
{
    int idx = blockIdx.x * 256 + threadIdx.x;
    if (idx < 384)
        g_boa[idx] = idx < 256 ? b_off[idx] : b_attn[idx - 256];

    float v; __half *hi, *lo; int o;
    if (idx < 65536) {                       // W_val [256x256]
        int k = idx >> 8, n = idx & 255;
        v = W_val[idx];
        o = (((k >> 6) << 8) + n) * 64 + (k & 63);
        hi = g_wv_hi; lo = g_wv_lo;
    } else if (idx < 65536 + 98304) {        // combined [256x384]
        int t = idx - 65536;
        int k = t / 384, n = t - k * 384;
        v = n < 256 ? W_off[k * 256 + n] : W_attn[k * 128 + (n - 256)];
        o = ((k >> 6) * 384 + n) * 64 + (k & 63);
        hi = g_woa_hi; lo = g_woa_lo;
    } else {                                 // W_out [256x256]
        int t = idx - 65536 - 98304;
        int k = t >> 8, n = t & 255;
        v = W_out[t];
        o = (((k >> 6) << 8) + n) * 64 + (k & 63);
        hi = g_wu_hi; lo = g_wu_lo;
    }
    __half h = __float2half_rn(v);
    hi[o] = h;
    lo[o] = __float2half_rn(v - __half2float(h));
}

// ---------------------------------------------------------------------------
// mma.sync fp16 GEMM, 2-term: C = A*(Bh+Bl) + bias. A fp32 -> fp16 in-kernel.
// CTA 128x64, 256 thr, warp tile 32x32, K 4x64 double-buffered.
// SMEM/buffer: A 16KB + Bh 8KB + Bl 8KB = 32KB; x2 = 64KB (2 CTA/SM easy).
// ---------------------------------------------------------------------------
template <int N, typename OutT>
__global__ __launch_bounds__(256, 2) void gemm_mma(
    const float* __restrict__ A,
    const __half* __restrict__ Bh_g, const __half* __restrict__ Bl_g,
    const float* __restrict__ bias, OutT* __restrict__ C)
{
    extern __shared__ char smem[];
    constexpr int BUF = 32768;
    constexpr int O_BH = 16384, O_BL = 24576;

    const int tid  = threadIdx.x;
    const int wid  = tid >> 5;
    const int lane = tid & 31;
    const int mBase = blockIdx.y * 128;
    const int nBase = blockIdx.x * 64;
    const int warpM = (wid & 3) * 32;
    const int warpN = (wid >> 2) * 32;

    const float4* Ag  = (const float4*)A;
    const uint4*  Bhg = (const uint4*)Bh_g;
    const uint4*  Blg = (const uint4*)Bl_g;

    float acc[2][4][4];
#pragma unroll
    for (int i = 0; i < 2; i++)
#pragma unroll
        for (int j = 0; j < 4; j++)
#pragma unroll
            for (int k = 0; k < 4; k++) acc[i][j][k] = 0.f;

    auto loadB = [&](int c, char* buf) {
        uint32_t bh = smem_u32(buf + O_BH), bl = smem_u32(buf + O_BL);
#pragma unroll
        for (int i = 0; i < 2; i++) {
            int f = tid + 256 * i;              // 0..511 per split
            int n = f >> 3, u = f & 7;
            uint32_t so = (n << 7) + (((u ^ (n & 7))) << 4);
            size_t gi = (size_t)(c * N + nBase + n) * 8 + u;
            cp16(bh + so, Bhg + gi);
            cp16(bl + so, Blg + gi);
        }
        asm volatile("cp.async.commit_group;" ::: "memory");
    };

    float4 apf[8];
    auto loadA = [&](int c) {
#pragma unroll
        for (int i = 0; i < 8; i++) {
            int f = tid + 256 * i;              // 0..2047 float4
            int row = f >> 4, q = f & 15;
            apf[i] = Ag[(size_t)(mBase + row) * 64 + c * 16 + q];
        }
    };
    auto storeA = [&](char* buf) {
#pragma unroll
        for (int i = 0; i < 8; i++) {
            int f = tid + 256 * i;
            int row = f >> 4, q = f & 15;
            float4 v = apf[i];
            __half2 h0 = __floats2half2_rn(v.x, v.y);
            __half2 h1 = __floats2half2_rn(v.z, v.w);
            uint32_t so = sw128(row * 128 + q * 8);
            *(__half2*)(buf + so)     = h0;
            *(__half2*)(buf + so + 4) = h1;
        }
    };

    loadB(0, smem);
    loadA(0);

    for (int c = 0; c < 4; c++) {
        char* buf = smem + (c & 1) * BUF;
        storeA(buf);
        if (c < 3) loadB(c + 1, smem + ((c + 1) & 1) * BUF);
        if (c < 3) asm volatile("cp.async.wait_group 1;" ::: "memory");
        else       asm volatile("cp.async.wait_group 0;" ::: "memory");
        __syncthreads();
        if (c < 3) loadA(c + 1);

        const uint32_t Ah = smem_u32(buf);
        const uint32_t Bh = Ah + O_BH;
        const uint32_t Bl = Ah + O_BL;

#pragma unroll
        for (int kk = 0; kk < 4; kk++) {
            uint32_t ah[2][4];
#pragma unroll
            for (int mi = 0; mi < 2; mi++) {
                int r = warpM + mi * 16 + (lane & 15);
                int u = kk * 2 + (lane >> 4);
                uint32_t off = (r << 7) + (((u ^ (r & 7))) << 4);
                ldsm4(ah[mi], Ah + off);
            }
            uint32_t bh[4][2], bl[4][2];
#pragma unroll
            for (int p = 0; p < 2; p++) {
                int r = warpN + p * 16 + ((lane >> 4) << 3) + (lane & 7);
                int u = kk * 2 + ((lane >> 3) & 1);
                uint32_t off = (r << 7) + (((u ^ (r & 7))) << 4);
                ldsm4(&bh[p * 2][0], Bh + off);
                ldsm4(&bl[p * 2][0], Bl + off);
            }
#pragma unroll
            for (int mi = 0; mi < 2; mi++)
#pragma unroll
                for (int j = 0; j < 4; j++) {
                    float* cc = acc[mi][j];
                    mma16816(cc, ah[mi], bh[j]);
                    mma16816(cc, ah[mi], bl[j]);
                }
        }
        __syncthreads();
    }

#pragma unroll
    for (int mi = 0; mi < 2; mi++) {
        int row0 = mBase + warpM + mi * 16 + (lane >> 2);
#pragma unroll
        for (int nj = 0; nj < 4; nj++) {
            int col = nBase + warpN + nj * 8 + (lane & 3) * 2;
            float bx = __ldg(bias + col), by = __ldg(bias + col + 1);
            float v00 = acc[mi][nj][0] + bx, v01 = acc[mi][nj][1] + by;
            float v10 = acc[mi][nj][2] + bx, v11 = acc[mi][nj][3] + by;
            if constexpr (sizeof(OutT) == 4) {
                *(float2*)((float*)C + (size_t)row0 * N + col)       = make_float2(v00, v01);
                *(float2*)((float*)C + (size_t)(row0 + 8) * N + col) = make_float2(v10, v11);
            } else {
                *(__half2*)((__half*)C + (size_t)row0 * N + col)       = __floats2half2_rn(v00, v01);
                *(__half2*)((__half*)C + (size_t)(row0 + 8) * N + col) = __floats2half2_rn(v10, v11);
            }
        }
    }
}

// ---------------------------------------------------------------------------
// Output GEMM: A already fp16 in chunk layout -> pure cp.async on both sides.
// ---------------------------------------------------------------------------
__global__ __launch_bounds__(256, 2) void gemm_pre(
    const __half* __restrict__ Ah_g,
    const __half* __restrict__ Bh_g, const __half* __restrict__ Bl_g,
    const float* __restrict__ bias, float* __restrict__ C)
{
    extern __shared__ char smem[];
    constexpr int BUF = 32768;
    constexpr int O_BH = 16384, O_BL = 24576;
    constexpr int N = 256;

    const int tid  = threadIdx.x;
    const int wid  = tid >> 5;
    const int lane = tid & 31;
    const int mBase = blockIdx.y * 128;
    const int nBase = blockIdx.x * 64;
    const int warpM = (wid & 3) * 32;
    const int warpN = (wid >> 2) * 32;

    const uint4* Ahg = (const uint4*)Ah_g;
    const uint4* Bhg = (const uint4*)Bh_g;
    const uint4* Blg = (const uint4*)Bl_g;

    float acc[2][4][4];
#pragma unroll
    for (int i = 0; i < 2; i++)
#pragma unroll
        for (int j = 0; j < 4; j++)
#pragma unroll
            for (int k = 0; k < 4; k++) acc[i][j][k] = 0.f;

    auto loadChunk = [&](int c, char* buf) {
        uint32_t ah = smem_u32(buf);
        uint32_t bh = ah + O_BH, bl = ah + O_BL;
#pragma unroll
        for (int i = 0; i < 4; i++) {           // A: 1024 uint4
            int f = tid + 256 * i;
            int row = f >> 3, u = f & 7;
            uint32_t so = (row << 7) + (((u ^ (row & 7))) << 4);
            size_t gi = (size_t)(c * MTOT + mBase + row) * 8 + u;
            cp16(ah + so, Ahg + gi);
        }
#pragma unroll
        for (int i = 0; i < 2; i++) {           // B: 512 uint4 per split
            int f = tid + 256 * i;
            int n = f >> 3, u = f & 7;
            uint32_t so = (n << 7) + (((u ^ (n & 7))) << 4);
            size_t gi = (size_t)(c * N + nBase + n) * 8 + u;
            cp16(bh + so, Bhg + gi);
            cp16(bl + so, Blg + gi);
        }
        asm volatile("cp.async.commit_group;" ::: "memory");
    };

    loadChunk(0, smem);

    for (int c = 0; c < 4; c++) {
        char* buf = smem + (c & 1) * BUF;
        if (c < 3) loadChunk(c + 1, smem + ((c + 1) & 1) * BUF);
        if (c < 3) asm volatile("cp.async.wait_group 1;" ::: "memory");
        else       asm volatile("cp.async.wait_group 0;" ::: "memory");
        __syncthreads();

        const uint32_t Ah = smem_u32(buf);
        const uint32_t Bh = Ah + O_BH;
        const uint32_t Bl = Ah + O_BL;

#pragma unroll
        for (int kk = 0; kk < 4; kk++) {
            uint32_t ah[2][4];
#pragma unroll
            for (int mi = 0; mi < 2; mi++) {
                int r = warpM + mi * 16 + (lane & 15);
                int u = kk * 2 + (lane >> 4);
                uint32_t off = (r << 7) + (((u ^ (r & 7))) << 4);
                ldsm4(ah[mi], Ah + off);
            }
            uint32_t bh[4][2], bl[4][2];
#pragma unroll
            for (int p = 0; p < 2; p++) {
                int r = warpN + p * 16 + ((lane >> 4) << 3) + (lane & 7);
                int u = kk * 2 + ((lane >> 3) & 1);
                uint32_t off = (r << 7) + (((u ^ (r & 7))) << 4);
                ldsm4(&bh[p * 2][0], Bh + off);
                ldsm4(&bl[p * 2][0], Bl + off);
            }
#pragma unroll
            for (int mi = 0; mi < 2; mi++)
#pragma unroll
                for (int j = 0; j < 4; j++) {
                    float* cc = acc[mi][j];
                    mma16816(cc, ah[mi], bh[j]);
                    mma16816(cc, ah[mi], bl[j]);
                }
        }
        __syncthreads();
    }

#pragma unroll
    for (int mi = 0; mi < 2; mi++) {
        int row0 = mBase + warpM + mi * 16 + (lane >> 2);
#pragma unroll
        for (int nj = 0; nj < 4; nj++) {
            int col = nBase + warpN + nj * 8 + (lane & 3) * 2;
            float bx = __ldg(bias + col), by = __ldg(bias + col + 1);
            *(float2*)(C + (size_t)row0 * N + col) =
                make_float2(acc[mi][nj][0] + bx, acc[mi][nj][1] + by);
            *(float2*)(C + (size_t)(row0 + 8) * N + col) =
                make_float2(acc[mi][nj][2] + bx, acc[mi][nj][3] + by);
        }
    }
}

// ---------------------------------------------------------------------------
// Fused softmax + deformable sampling (R5 structure).
// Block = 256 threads = 2 query rows x 8 heads = 16 head-slots.
// Phase 2: warp serves 2 head-slots, 16 lanes per slot, lane = 2 channels
// (half2). Output written as single fp16 in the out-GEMM chunk layout.
// ---------------------------------------------------------------------------
__global__ __launch_bounds__(256) void msda_sample(const float* __restrict__ refp)
{
    __shared__ float4 sw[16][17];
    __shared__ int4   si[16][17];

    const int tid = threadIdx.x;
    const int rowBase = blockIdx.x * 2;

    // ---- Phase 1: per-(head,point) setup ----
    {
        const int hs  = tid >> 4;        // head slot 0..15
        const int s   = tid & 15;        // point (lvl*4 + pt)
        const int row = rowBase + (hs >> 3);
        const int h   = hs & 7;
        const int b   = row / LQ;

        const int lvl = s >> 2;
        const int Wl  = 64 >> lvl;
        const int st  = (16384 - (16384 >> (2 * lvl))) / 3;

        const float refx = refp[row * 8 + lvl * 2 + 0];
        const float refy = refp[row * 8 + lvl * 2 + 1];
        const int obase  = row * 384 + ((h * 16 + s) * 2);
        const float offx = g_oa[obase + 0];
        const float offy = g_oa[obase + 1];

        const float x = refx * (float)Wl + offx - 0.5f;
        const float y = refy * (float)Wl + offy - 0.5f;
        const float fx = floorf(x), fy = floorf(y);
        const float lx = x - fx,   ly = y - fy;
        const int x0 = (int)fx, y0 = (int)fy;
        const int x1 = x0 + 1,  y1 = y0 + 1;

        const float logit = g_oa[row * 384 + 256 + h * 16 + s];
        float mx = logit;
#pragma unroll
        for (int o = 8; o; o >>= 1) mx = fmaxf(mx, __shfl_xor_sync(~0u, mx, o, 16));
        const float e = __expf(logit - mx);
        float sum = e;
#pragma unroll
        for (int o = 8; o; o >>= 1) sum += __shfl_xor_sync(~0u, sum, o, 16);
        const float wa = e / sum;

        const bool vx0 = (unsigned)x0 < (unsigned)Wl;
        const bool vx1 = (unsigned)x1 < (unsigned)Wl;
        const bool vy0 = (unsigned)y0 < (unsigned)Wl;
        const bool vy1 = (unsigned)y1 < (unsigned)Wl;
        const int cx0 = min(max(x0, 0), Wl - 1);
        const int cx1 = min(max(x1, 0), Wl - 1);
        const int cy0 = min(max(y0, 0), Wl - 1);
        const int cy1 = min(max(y1, 0), Wl - 1);
        const int rb  = b * LIN + st;

        si[hs][s] = make_int4(rb + cy0 * Wl + cx0, rb + cy0 * Wl + cx1,
                              rb + cy1 * Wl + cx0, rb + cy1 * Wl + cx1);
        sw[hs][s] = make_float4(
            wa * (1.f - lx) * (1.f - ly) * (float)(vx0 && vy0),
            wa * lx         * (1.f - ly) * (float)(vx1 && vy0),
            wa * (1.f - lx) * ly         * (float)(vx0 && vy1),
            wa * lx         * ly         * (float)(vx1 && vy1));
    }
    __syncthreads();

    // ---- Phase 2: gather + accumulate ----
    const int wid  = tid >> 5;
    const int lane = tid & 31;
    const int hs   = wid * 2 + (lane >> 4);
    const int row  = rowBase + (hs >> 3);
    const int h    = hs & 7;
    const int c2   = (lane & 15) * 2;          // channel pair

    const __half* __restrict__ vp = g_value_h + h * 32 + c2;
    float ax = 0.f, ay = 0.f;
#pragma unroll 4
    for (int t = 0; t < 16; t++) {
        const float4 w  = sw[hs][t];
        const int4   id = si[hs][t];
        const float2 f0 = __half22float2(*(const __half2*)(vp + (size_t)id.x * 256));
        const float2 f1 = __half22float2(*(const __half2*)(vp + (size_t)id.y * 256));
        const float2 f2 = __half22float2(*(const __half2*)(vp + (size_t)id.z * 256));
        const float2 f3 = __half22float2(*(const __half2*)(vp + (size_t)id.w * 256));
        ax += w.x * f0.x + w.y * f1.x + w.z * f2.x + w.w * f3.x;
        ay += w.x * f0.y + w.y * f1.y + w.z * f2.y + w.w * f3.y;
    }

    // single fp16 core in out-GEMM chunk layout (k = h*32 + c2)
    size_t o = ((size_t)(h >> 1) * MTOT + row) * 64 + (h & 1) * 32 + c2;
    *(__half2*)(g_core_h + o) = __floats2half2_rn(ax, ay);
}

// ---------------------------------------------------------------------------
extern "C" void kernel_launch(void* const* d_in, const int* in_sizes, int n_in,
                              void* d_out, int out_size)
{
    const float* query  = (const float*)d_in[0];
    const float* refp   = (const float*)d_in[1];
    const float* inpf   = (const float*)d_in[2];
    const float* W_val  = (const float*)d_in[5];
    const float* b_val  = (const float*)d_in[6];
    const float* W_off  = (const float*)d_in[7];
    const float* b_off  = (const float*)d_in[8];
    const float* W_attn = (const float*)d_in[9];
    const float* b_attn = (const float*)d_in[10];
    const float* W_out  = (const float*)d_in[11];
    const float* b_out  = (const float*)d_in[12];
    float* out = (float*)d_out;

    __half *p_val, *p_core;  float *p_oa, *p_boa;
    cudaGetSymbolAddress((void**)&p_val,  g_value_h);
    cudaGetSymbolAddress((void**)&p_oa,   g_oa);
    cudaGetSymbolAddress((void**)&p_boa,  g_boa);
    cudaGetSymbolAddress((void**)&p_core, g_core_h);
    __half *wv_h, *wv_l, *woa_h, *woa_l, *wu_h, *wu_l;
    cudaGetSymbolAddress((void**)&wv_h,  g_wv_hi);  cudaGetSymbolAddress((void**)&wv_l,  g_wv_lo);
    cudaGetSymbolAddress((void**)&woa_h, g_woa_hi); cudaGetSymbolAddress((void**)&woa_l, g_woa_lo);
    cudaGetSymbolAddress((void**)&wu_h,  g_wu_hi);  cudaGetSymbolAddress((void**)&wu_l,  g_wu_lo);

    constexpr int SMEM = 65536;
    cudaFuncSetAttribute(gemm_mma<256, __half>, cudaFuncAttributeMaxDynamicSharedMemorySize, SMEM);
    cudaFuncSetAttribute(gemm_mma<384, float>,  cudaFuncAttributeMaxDynamicSharedMemorySize, SMEM);
    cudaFuncSetAttribute(gemm_pre,              cudaFuncAttributeMaxDynamicSharedMemorySize, SMEM);

    prep_all<<<896, 256>>>(W_val, W_off, W_attn, W_out, b_off, b_attn);

    const int MT = MTOT / 128;  // 340
    gemm_mma<256, __half><<<dim3(4, MT), 256, SMEM>>>(inpf,  wv_h,  wv_l,  b_val, p_val);
    gemm_mma<384, float ><<<dim3(6, MT), 256, SMEM>>>(query, woa_h, woa_l, p_boa, p_oa);

    msda_sample<<<MTOT / 2, 256>>>(refp);

    gemm_pre<<<dim3(4, MT), 256, SMEM>>>(p_core, wu_h, wu_l, b_out, out);
}

// round 11
// speedup vs baseline: 2.3670x; 1.0829x over previous
#include <cuda_runtime.h>
#include <cuda_bf16.h>
#include <cuda_fp16.h>
#include <cstdint>

// Problem constants (fixed by the dataset)
#define BB   8
#define LQ   5440
#define LIN  5440
#define DM   256
#define NH   8
#define MTOT (BB * LQ)   // 43520

// ---------------------------------------------------------------------------
// Scratch (device globals; allocation-free per harness rules)
// ---------------------------------------------------------------------------
__device__ __align__(16) __half g_value_h[MTOT * DM];       // fp16 value
__device__ __align__(16) float  g_oa  [MTOT * 384];         // off(256) + attn logits(128)
// core as single fp16, chunk-contiguous GEMM layout:
// half index = ((k>>6)*MTOT + row)*64 + (k&63),  k = h*32 + ch
__device__ __align__(16) __half g_core_h[MTOT * DM];

// Pre-transposed fp16 weights, chunk-contiguous layout:
// element index = ((k>>6)*N + n)*64 + (k&63)   (64-wide K chunks)
__device__ __align__(16) __half g_wv [DM * DM];
__device__ __align__(16) __half g_woa[DM * 384];
__device__ __align__(16) __half g_wu [DM * DM];
__device__ __align__(16) float g_boa[384];

// ---------------------------------------------------------------------------
// Helpers (base-target ISA only: ldmatrix / cp.async / mma.sync)
// ---------------------------------------------------------------------------
__device__ __forceinline__ uint32_t smem_u32(const void* p) {
    uint32_t a;
    asm("{ .reg .u64 t; cvta.to.shared.u64 t, %1; cvt.u32.u64 %0, t; }"
        : "=r"(a) : "l"(p));
    return a;
}
__device__ __forceinline__ void ldsm4(uint32_t* d, uint32_t addr) {
    asm volatile("ldmatrix.sync.aligned.m8n8.x4.shared.b16 {%0,%1,%2,%3}, [%4];"
                 : "=r"(d[0]), "=r"(d[1]), "=r"(d[2]), "=r"(d[3]) : "r"(addr));
}
__device__ __forceinline__ void mma16816(float* c, const uint32_t* a,
                                         const uint32_t* b) {
    asm volatile(
        "mma.sync.aligned.m16n8k16.row.col.f32.f16.f16.f32 "
        "{%0,%1,%2,%3}, {%4,%5,%6,%7}, {%8,%9}, {%0,%1,%2,%3};"
        : "+f"(c[0]), "+f"(c[1]), "+f"(c[2]), "+f"(c[3])
        : "r"(a[0]), "r"(a[1]), "r"(a[2]), "r"(a[3]), "r"(b[0]), "r"(b[1]));
}
__device__ __forceinline__ void cp16(uint32_t dst, const void* src) {
    asm volatile("cp.async.cg.shared.global [%0], [%1], 16;"
                 :: "r"(dst), "l"(src) : "memory");
}
__device__ __forceinline__ uint32_t sw128(uint32_t b) { return b ^ ((b >> 3) & 0x70); }

// ---------------------------------------------------------------------------
// Fused weight prep: W (val / off+attn combined / out) transposed to fp16
// chunk-contiguous layout, plus combined bias.
// ---------------------------------------------------------------------------
__global__ void prep_all(const float* __restrict__ W_val,
                         const float* __restrict__ W_off,
                         const float* __restrict__ W_attn,
                         const float* __restrict__ W_out,
                         const float* __restrict__ b_off,
                         const float* __restrict__ b_attn)
{
    int idx = blockIdx.x * 256 + threadIdx.x;
    if (idx < 384)
        g_boa[idx] = idx < 256 ? b_off[idx] : b_attn[idx - 256];

    float v; __half* w; int o;
    if (idx < 65536) {                       // W_val [256x256]
        int k = idx >> 8, n = idx & 255;
        v = W_val[idx];
        o = (((k >> 6) << 8) + n) * 64 + (k & 63);
        w = g_wv;
    } else if (idx < 65536 + 98304) {        // combined [256x384]
        int t = idx - 65536;
        int k = t / 384, n = t - k * 384;
        v = n < 256 ? W_off[k * 256 + n] : W_attn[k * 128 + (n - 256)];
        o = ((k >> 6) * 384 + n) * 64 + (k & 63);
        w = g_woa;
    } else {                                 // W_out [256x256]
        int t = idx - 65536 - 98304;
        int k = t >> 8, n = t & 255;
        v = W_out[t];
        o = (((k >> 6) << 8) + n) * 64 + (k & 63);
        w = g_wu;
    }
    w[o] = __float2half_rn(v);
}

// ---------------------------------------------------------------------------
// mma.sync fp16 GEMM: C = A*B + bias. A fp32 -> fp16 in-kernel.
// CTA 128x64, 256 thr, warp tile 32x32, K 4x64 double-buffered.
// SMEM/buffer: A 16KB + B 8KB = 24KB; x2 = 48KB (2 CTA/SM).
// ---------------------------------------------------------------------------
template <int N, typename OutT>
__global__ __launch_bounds__(256, 2) void gemm_mma(
    const float* __restrict__ A,
    const __half* __restrict__ B_g,
    const float* __restrict__ bias, OutT* __restrict__ C)
{
    extern __shared__ char smem[];
    constexpr int BUF = 24576;
    constexpr int O_B = 16384;

    const int tid  = threadIdx.x;
    const int wid  = tid >> 5;
    const int lane = tid & 31;
    const int mBase = blockIdx.y * 128;
    const int nBase = blockIdx.x * 64;
    const int warpM = (wid & 3) * 32;
    const int warpN = (wid >> 2) * 32;

    const float4* Ag = (const float4*)A;
    const uint4*  Bg = (const uint4*)B_g;

    float acc[2][4][4];
#pragma unroll
    for (int i = 0; i < 2; i++)
#pragma unroll
        for (int j = 0; j < 4; j++)
#pragma unroll
            for (int k = 0; k < 4; k++) acc[i][j][k] = 0.f;

    auto loadB = [&](int c, char* buf) {
        uint32_t bs = smem_u32(buf + O_B);
        {
            int f = tid;                        // 512 uint4 total
            int n = f >> 3, u = f & 7;
            uint32_t so = (n << 7) + (((u ^ (n & 7))) << 4);
            size_t gi = (size_t)(c * N + nBase + n) * 8 + u;
            cp16(bs + so, Bg + gi);
        }
        {
            int f = tid + 256;
            int n = f >> 3, u = f & 7;
            uint32_t so = (n << 7) + (((u ^ (n & 7))) << 4);
            size_t gi = (size_t)(c * N + nBase + n) * 8 + u;
            cp16(bs + so, Bg + gi);
        }
        asm volatile("cp.async.commit_group;" ::: "memory");
    };

    float4 apf[8];
    auto loadA = [&](int c) {
#pragma unroll
        for (int i = 0; i < 8; i++) {
            int f = tid + 256 * i;              // 0..2047 float4
            int row = f >> 4, q = f & 15;
            apf[i] = Ag[(size_t)(mBase + row) * 64 + c * 16 + q];
        }
    };
    auto storeA = [&](char* buf) {
#pragma unroll
        for (int i = 0; i < 8; i++) {
            int f = tid + 256 * i;
            int row = f >> 4, q = f & 15;
            float4 v = apf[i];
            __half2 h0 = __floats2half2_rn(v.x, v.y);
            __half2 h1 = __floats2half2_rn(v.z, v.w);
            uint32_t so = sw128(row * 128 + q * 8);
            *(__half2*)(buf + so)     = h0;
            *(__half2*)(buf + so + 4) = h1;
        }
    };

    loadB(0, smem);
    loadA(0);

    for (int c = 0; c < 4; c++) {
        char* buf = smem + (c & 1) * BUF;
        storeA(buf);
        if (c < 3) loadB(c + 1, smem + ((c + 1) & 1) * BUF);
        if (c < 3) asm volatile("cp.async.wait_group 1;" ::: "memory");
        else       asm volatile("cp.async.wait_group 0;" ::: "memory");
        __syncthreads();
        if (c < 3) loadA(c + 1);

        const uint32_t Ah = smem_u32(buf);
        const uint32_t Bs = Ah + O_B;

#pragma unroll
        for (int kk = 0; kk < 4; kk++) {
            uint32_t ah[2][4];
#pragma unroll
            for (int mi = 0; mi < 2; mi++) {
                int r = warpM + mi * 16 + (lane & 15);
                int u = kk * 2 + (lane >> 4);
                uint32_t off = (r << 7) + (((u ^ (r & 7))) << 4);
                ldsm4(ah[mi], Ah + off);
            }
            uint32_t bh[4][2];
#pragma unroll
            for (int p = 0; p < 2; p++) {
                int r = warpN + p * 16 + ((lane >> 4) << 3) + (lane & 7);
                int u = kk * 2 + ((lane >> 3) & 1);
                uint32_t off = (r << 7) + (((u ^ (r & 7))) << 4);
                ldsm4(&bh[p * 2][0], Bs + off);
            }
#pragma unroll
            for (int mi = 0; mi < 2; mi++)
#pragma unroll
                for (int j = 0; j < 4; j++)
                    mma16816(acc[mi][j], ah[mi], bh[j]);
        }
        __syncthreads();
    }

#pragma unroll
    for (int mi = 0; mi < 2; mi++) {
        int row0 = mBase + warpM + mi * 16 + (lane >> 2);
#pragma unroll
        for (int nj = 0; nj < 4; nj++) {
            int col = nBase + warpN + nj * 8 + (lane & 3) * 2;
            float bx = __ldg(bias + col), by = __ldg(bias + col + 1);
            float v00 = acc[mi][nj][0] + bx, v01 = acc[mi][nj][1] + by;
            float v10 = acc[mi][nj][2] + bx, v11 = acc[mi][nj][3] + by;
            if constexpr (sizeof(OutT) == 4) {
                *(float2*)((float*)C + (size_t)row0 * N + col)       = make_float2(v00, v01);
                *(float2*)((float*)C + (size_t)(row0 + 8) * N + col) = make_float2(v10, v11);
            } else {
                *(__half2*)((__half*)C + (size_t)row0 * N + col)       = __floats2half2_rn(v00, v01);
                *(__half2*)((__half*)C + (size_t)(row0 + 8) * N + col) = __floats2half2_rn(v10, v11);
            }
        }
    }
}

// ---------------------------------------------------------------------------
// Output GEMM: A already fp16 in chunk layout -> pure cp.async on both sides.
// ---------------------------------------------------------------------------
__global__ __launch_bounds__(256, 2) void gemm_pre(
    const __half* __restrict__ A_g,
    const __half* __restrict__ B_g,
    const float* __restrict__ bias, float* __restrict__ C)
{
    extern __shared__ char smem[];
    constexpr int BUF = 24576;
    constexpr int O_B = 16384;
    constexpr int N = 256;

    const int tid  = threadIdx.x;
    const int wid  = tid >> 5;
    const int lane = tid & 31;
    const int mBase = blockIdx.y * 128;
    const int nBase = blockIdx.x * 64;
    const int warpM = (wid & 3) * 32;
    const int warpN = (wid >> 2) * 32;

    const uint4* Ag = (const uint4*)A_g;
    const uint4* Bg = (const uint4*)B_g;

    float acc[2][4][4];
#pragma unroll
    for (int i = 0; i < 2; i++)
#pragma unroll
        for (int j = 0; j < 4; j++)
#pragma unroll
            for (int k = 0; k < 4; k++) acc[i][j][k] = 0.f;

    auto loadChunk = [&](int c, char* buf) {
        uint32_t as = smem_u32(buf);
        uint32_t bs = as + O_B;
#pragma unroll
        for (int i = 0; i < 4; i++) {           // A: 1024 uint4
            int f = tid + 256 * i;
            int row = f >> 3, u = f & 7;
            uint32_t so = (row << 7) + (((u ^ (row & 7))) << 4);
            size_t gi = (size_t)(c * MTOT + mBase + row) * 8 + u;
            cp16(as + so, Ag + gi);
        }
#pragma unroll
        for (int i = 0; i < 2; i++) {           // B: 512 uint4
            int f = tid + 256 * i;
            int n = f >> 3, u = f & 7;
            uint32_t so = (n << 7) + (((u ^ (n & 7))) << 4);
            size_t gi = (size_t)(c * N + nBase + n) * 8 + u;
            cp16(bs + so, Bg + gi);
        }
        asm volatile("cp.async.commit_group;" ::: "memory");
    };

    loadChunk(0, smem);

    for (int c = 0; c < 4; c++) {
        char* buf = smem + (c & 1) * BUF;
        if (c < 3) loadChunk(c + 1, smem + ((c + 1) & 1) * BUF);
        if (c < 3) asm volatile("cp.async.wait_group 1;" ::: "memory");
        else       asm volatile("cp.async.wait_group 0;" ::: "memory");
        __syncthreads();

        const uint32_t Ah = smem_u32(buf);
        const uint32_t Bs = Ah + O_B;

#pragma unroll
        for (int kk = 0; kk < 4; kk++) {
            uint32_t ah[2][4];
#pragma unroll
            for (int mi = 0; mi < 2; mi++) {
                int r = warpM + mi * 16 + (lane & 15);
                int u = kk * 2 + (lane >> 4);
                uint32_t off = (r << 7) + (((u ^ (r & 7))) << 4);
                ldsm4(ah[mi], Ah + off);
            }
            uint32_t bh[4][2];
#pragma unroll
            for (int p = 0; p < 2; p++) {
                int r = warpN + p * 16 + ((lane >> 4) << 3) + (lane & 7);
                int u = kk * 2 + ((lane >> 3) & 1);
                uint32_t off = (r << 7) + (((u ^ (r & 7))) << 4);
                ldsm4(&bh[p * 2][0], Bs + off);
            }
#pragma unroll
            for (int mi = 0; mi < 2; mi++)
#pragma unroll
                for (int j = 0; j < 4; j++)
                    mma16816(acc[mi][j], ah[mi], bh[j]);
        }
        __syncthreads();
    }

#pragma unroll
    for (int mi = 0; mi < 2; mi++) {
        int row0 = mBase + warpM + mi * 16 + (lane >> 2);
#pragma unroll
        for (int nj = 0; nj < 4; nj++) {
            int col = nBase + warpN + nj * 8 + (lane & 3) * 2;
            float bx = __ldg(bias + col), by = __ldg(bias + col + 1);
            *(float2*)(C + (size_t)row0 * N + col) =
                make_float2(acc[mi][nj][0] + bx, acc[mi][nj][1] + by);
            *(float2*)(C + (size_t)(row0 + 8) * N + col) =
                make_float2(acc[mi][nj][2] + bx, acc[mi][nj][3] + by);
        }
    }
}

// ---------------------------------------------------------------------------
// Fused softmax + deformable sampling (proven R5 structure).
// Block = 256 threads = 2 query rows x 8 heads = 16 head-slots.
// Phase 2: warp serves 2 head-slots, 16 lanes per slot, lane = 2 channels
// (half2). Output written as single fp16 in the out-GEMM chunk layout.
// ---------------------------------------------------------------------------
__global__ __launch_bounds__(256) void msda_sample(const float* __restrict__ refp)
{
    __shared__ float4 sw[16][17];
    __shared__ int4   si[16][17];

    const int tid = threadIdx.x;
    const int rowBase = blockIdx.x * 2;

    // ---- Phase 1: per-(head,point) setup ----
    {
        const int hs  = tid >> 4;        // head slot 0..15
        const int s   = tid & 15;        // point (lvl*4 + pt)
        const int row = rowBase + (hs >> 3);
        const int h   = hs & 7;
        const int b   = row / LQ;

        const int lvl = s >> 2;
        const int Wl  = 64 >> lvl;
        const int st  = (16384 - (16384 >> (2 * lvl))) / 3;

        const float refx = refp[row * 8 + lvl * 2 + 0];
        const float refy = refp[row * 8 + lvl * 2 + 1];
        const int obase  = row * 384 + ((h * 16 + s) * 2);
        const float offx = g_oa[obase + 0];
        const float offy = g_oa[obase + 1];

        const float x = refx * (float)Wl + offx - 0.5f;
        const float y = refy * (float)Wl + offy - 0.5f;
        const float fx = floorf(x), fy = floorf(y);
        const float lx = x - fx,   ly = y - fy;
        const int x0 = (int)fx, y0 = (int)fy;
        const int x1 = x0 + 1,  y1 = y0 + 1;

        const float logit = g_oa[row * 384 + 256 + h * 16 + s];
        float mx = logit;
#pragma unroll
        for (int o = 8; o; o >>= 1) mx = fmaxf(mx, __shfl_xor_sync(~0u, mx, o, 16));
        const float e = __expf(logit - mx);
        float sum = e;
#pragma unroll
        for (int o = 8; o; o >>= 1) sum += __shfl_xor_sync(~0u, sum, o, 16);
        const float wa = e / sum;

        const bool vx0 = (unsigned)x0 < (unsigned)Wl;
        const bool vx1 = (unsigned)x1 < (unsigned)Wl;
        const bool vy0 = (unsigned)y0 < (unsigned)Wl;
        const bool vy1 = (unsigned)y1 < (unsigned)Wl;
        const int cx0 = min(max(x0, 0), Wl - 1);
        const int cx1 = min(max(x1, 0), Wl - 1);
        const int cy0 = min(max(y0, 0), Wl - 1);
        const int cy1 = min(max(y1, 0), Wl - 1);
        const int rb  = b * LIN + st;

        si[hs][s] = make_int4(rb + cy0 * Wl + cx0, rb + cy0 * Wl + cx1,
                              rb + cy1 * Wl + cx0, rb + cy1 * Wl + cx1);
        sw[hs][s] = make_float4(
            wa * (1.f - lx) * (1.f - ly) * (float)(vx0 && vy0),
            wa * lx         * (1.f - ly) * (float)(vx1 && vy0),
            wa * (1.f - lx) * ly         * (float)(vx0 && vy1),
            wa * lx         * ly         * (float)(vx1 && vy1));
    }
    __syncthreads();

    // ---- Phase 2: gather + accumulate ----
    const int wid  = tid >> 5;
    const int lane = tid & 31;
    const int hs   = wid * 2 + (lane >> 4);
    const int row  = rowBase + (hs >> 3);
    const int h    = hs & 7;
    const int c2   = (lane & 15) * 2;          // channel pair

    const __half* __restrict__ vp = g_value_h + h * 32 + c2;
    float ax = 0.f, ay = 0.f;
#pragma unroll 4
    for (int t = 0; t < 16; t++) {
        const float4 w  = sw[hs][t];
        const int4   id = si[hs][t];
        const float2 f0 = __half22float2(*(const __half2*)(vp + (size_t)id.x * 256));
        const float2 f1 = __half22float2(*(const __half2*)(vp + (size_t)id.y * 256));
        const float2 f2 = __half22float2(*(const __half2*)(vp + (size_t)id.z * 256));
        const float2 f3 = __half22float2(*(const __half2*)(vp + (size_t)id.w * 256));
        ax += w.x * f0.x + w.y * f1.x + w.z * f2.x + w.w * f3.x;
        ay += w.x * f0.y + w.y * f1.y + w.z * f2.y + w.w * f3.y;
    }

    // single fp16 core in out-GEMM chunk layout (k = h*32 + c2)
    size_t o = ((size_t)(h >> 1) * MTOT + row) * 64 + (h & 1) * 32 + c2;
    *(__half2*)(g_core_h + o) = __floats2half2_rn(ax, ay);
}

// ---------------------------------------------------------------------------
extern "C" void kernel_launch(void* const* d_in, const int* in_sizes, int n_in,
                              void* d_out, int out_size)
{
    const float* query  = (const float*)d_in[0];
    const float* refp   = (const float*)d_in[1];
    const float* inpf   = (const float*)d_in[2];
    const float* W_val  = (const float*)d_in[5];
    const float* b_val  = (const float*)d_in[6];
    const float* W_off  = (const float*)d_in[7];
    const float* b_off  = (const float*)d_in[8];
    const float* W_attn = (const float*)d_in[9];
    const float* b_attn = (const float*)d_in[10];
    const float* W_out  = (const float*)d_in[11];
    const float* b_out  = (const float*)d_in[12];
    float* out = (float*)d_out;

    __half *p_val, *p_core;  float *p_oa, *p_boa;
    cudaGetSymbolAddress((void**)&p_val,  g_value_h);
    cudaGetSymbolAddress((void**)&p_oa,   g_oa);
    cudaGetSymbolAddress((void**)&p_boa,  g_boa);
    cudaGetSymbolAddress((void**)&p_core, g_core_h);
    __half *wv, *woa, *wu;
    cudaGetSymbolAddress((void**)&wv,  g_wv);
    cudaGetSymbolAddress((void**)&woa, g_woa);
    cudaGetSymbolAddress((void**)&wu,  g_wu);

    constexpr int SMEM = 49152;
    cudaFuncSetAttribute(gemm_mma<256, __half>, cudaFuncAttributeMaxDynamicSharedMemorySize, SMEM);
    cudaFuncSetAttribute(gemm_mma<384, float>,  cudaFuncAttributeMaxDynamicSharedMemorySize, SMEM);
    cudaFuncSetAttribute(gemm_pre,              cudaFuncAttributeMaxDynamicSharedMemorySize, SMEM);

    prep_all<<<896, 256>>>(W_val, W_off, W_attn, W_out, b_off, b_attn);

    const int MT = MTOT / 128;  // 340
    gemm_mma<256, __half><<<dim3(4, MT), 256, SMEM>>>(inpf,  wv,  b_val, p_val);
    gemm_mma<384, float ><<<dim3(6, MT), 256, SMEM>>>(query, woa, p_boa, p_oa);

    msda_sample<<<MTOT / 2, 256>>>(refp);

    gemm_pre<<<dim3(4, MT), 256, SMEM>>>(p_core, wu, b_out, out);
}

// round 12
// speedup vs baseline: 2.5270x; 1.0676x over previous
#include <cuda_runtime.h>
#include <cuda_bf16.h>
#include <cuda_fp16.h>
#include <cstdint>

// Problem constants (fixed by the dataset)
#define BB   8
#define LQ   5440
#define LIN  5440
#define DM   256
#define NH   8
#define MTOT (BB * LQ)   // 43520

// ---------------------------------------------------------------------------
// Scratch (device globals; allocation-free per harness rules)
// ---------------------------------------------------------------------------
__device__ __align__(16) __half g_value_h[MTOT * DM];       // fp16 value
__device__ __align__(16) float  g_oa  [MTOT * 384];         // off(256) + attn logits(128)
// fp16 activations in chunk-contiguous GEMM layout:
// half index = ((k>>6)*MTOT + row)*64 + (k&63)
__device__ __align__(16) __half g_core_h[MTOT * DM];
__device__ __align__(16) __half g_if_h  [MTOT * DM];        // inpf fp16
__device__ __align__(16) __half g_q_h   [MTOT * DM];        // query fp16

// Pre-transposed fp16 weights, chunk-contiguous layout:
// element index = ((k>>6)*N + n)*64 + (k&63)   (64-wide K chunks)
__device__ __align__(16) __half g_wv [DM * DM];
__device__ __align__(16) __half g_woa[DM * 384];
__device__ __align__(16) __half g_wu [DM * DM];
__device__ __align__(16) float g_boa[384];

// ---------------------------------------------------------------------------
// Helpers
// ---------------------------------------------------------------------------
__device__ __forceinline__ uint32_t smem_u32(const void* p) {
    uint32_t a;
    asm("{ .reg .u64 t; cvta.to.shared.u64 t, %1; cvt.u32.u64 %0, t; }"
        : "=r"(a) : "l"(p));
    return a;
}
__device__ __forceinline__ void ldsm4(uint32_t* d, uint32_t addr) {
    asm volatile("ldmatrix.sync.aligned.m8n8.x4.shared.b16 {%0,%1,%2,%3}, [%4];"
                 : "=r"(d[0]), "=r"(d[1]), "=r"(d[2]), "=r"(d[3]) : "r"(addr));
}
__device__ __forceinline__ void mma16816(float* c, const uint32_t* a,
                                         const uint32_t* b) {
    asm volatile(
        "mma.sync.aligned.m16n8k16.row.col.f32.f16.f16.f32 "
        "{%0,%1,%2,%3}, {%4,%5,%6,%7}, {%8,%9}, {%0,%1,%2,%3};"
        : "+f"(c[0]), "+f"(c[1]), "+f"(c[2]), "+f"(c[3])
        : "r"(a[0]), "r"(a[1]), "r"(a[2]), "r"(a[3]), "r"(b[0]), "r"(b[1]));
}
__device__ __forceinline__ void cp16(uint32_t dst, const void* src) {
    asm volatile("cp.async.cg.shared.global [%0], [%1], 16;"
                 :: "r"(dst), "l"(src) : "memory");
}

// ---------------------------------------------------------------------------
// Weight prep (transpose + fp16, chunk layout) + combined bias
// ---------------------------------------------------------------------------
__global__ void prep_all(const float* __restrict__ W_val,
                         const float* __restrict__ W_off,
                         const float* __restrict__ W_attn,
                         const float* __restrict__ W_out,
                         const float* __restrict__ b_off,
                         const float* __restrict__ b_attn)
{
    int idx = blockIdx.x * 256 + threadIdx.x;
    if (idx < 384)
        g_boa[idx] = idx < 256 ? b_off[idx] : b_attn[idx - 256];

    float v; __half* w; int o;
    if (idx < 65536) {                       // W_val [256x256]
        int k = idx >> 8, n = idx & 255;
        v = W_val[idx];
        o = (((k >> 6) << 8) + n) * 64 + (k & 63);
        w = g_wv;
    } else if (idx < 65536 + 98304) {        // combined [256x384]
        int t = idx - 65536;
        int k = t / 384, n = t - k * 384;
        v = n < 256 ? W_off[k * 256 + n] : W_attn[k * 128 + (n - 256)];
        o = ((k >> 6) * 384 + n) * 64 + (k & 63);
        w = g_woa;
    } else {                                 // W_out [256x256]
        int t = idx - 65536 - 98304;
        int k = t >> 8, n = t & 255;
        v = W_out[t];
        o = (((k >> 6) << 8) + n) * 64 + (k & 63);
        w = g_wu;
    }
    w[o] = __float2half_rn(v);
}

// ---------------------------------------------------------------------------
// Activation convert: inpf + query fp32 -> fp16 chunk-contiguous layout.
// thread: u = t&7 (8-half group), q = t>>3; row = q % MTOT; cc = q / MTOT;
// tensor = cc>>2, chunk c = cc&3. Coalesced reads (32B/thr) + writes (16B/thr).
// ---------------------------------------------------------------------------
__global__ __launch_bounds__(256) void convert_act(
    const float* __restrict__ inpf, const float* __restrict__ query)
{
    const int t  = blockIdx.x * 256 + threadIdx.x;
    const int u  = t & 7;
    const int q  = t >> 3;
    const int row = q % MTOT;
    const int cc  = q / MTOT;          // 0..7
    const int c   = cc & 3;
    const float* src = (cc < 4) ? inpf : query;
    __half* dst      = (cc < 4) ? g_if_h : g_q_h;

    const float4* sp = (const float4*)(src + (size_t)row * 256 + c * 64 + u * 8);
    float4 v0 = sp[0], v1 = sp[1];
    __half2 h[4];
    h[0] = __floats2half2_rn(v0.x, v0.y);
    h[1] = __floats2half2_rn(v0.z, v0.w);
    h[2] = __floats2half2_rn(v1.x, v1.y);
    h[3] = __floats2half2_rn(v1.z, v1.w);
    *(uint4*)(dst + ((size_t)c * MTOT + row) * 64 + u * 8) = *(uint4*)h;
}

// ---------------------------------------------------------------------------
// fp16 GEMM, pure cp.async: C[M,N] = A*B + bias.
// A fp16 chunk layout, B fp16 chunk layout. CTA 128x128, 256 thr (8 warps;
// warp tile 32x64). K: 4 chunks of 64, double-buffered (32KB/buf, 64KB total
// -> 2 CTAs/SM).
// ---------------------------------------------------------------------------
template <int N, typename OutT>
__global__ __launch_bounds__(256, 2) void gemm_f16(
    const __half* __restrict__ A_g,
    const __half* __restrict__ B_g,
    const float* __restrict__ bias, OutT* __restrict__ C)
{
    extern __shared__ char smem[];
    constexpr int BUF = 32768;
    constexpr int O_B = 16384;

    const int tid  = threadIdx.x;
    const int wid  = tid >> 5;
    const int lane = tid & 31;
    const int mBase = blockIdx.y * 128;
    const int nBase = blockIdx.x * 128;
    const int warpM = (wid & 3) * 32;
    const int warpN = (wid >> 2) * 64;

    const uint4* Ag = (const uint4*)A_g;
    const uint4* Bg = (const uint4*)B_g;

    float acc[2][8][4];
#pragma unroll
    for (int i = 0; i < 2; i++)
#pragma unroll
        for (int j = 0; j < 8; j++)
#pragma unroll
            for (int k = 0; k < 4; k++) acc[i][j][k] = 0.f;

    auto loadChunk = [&](int c, char* buf) {
        uint32_t as = smem_u32(buf);
        uint32_t bs = as + O_B;
#pragma unroll
        for (int i = 0; i < 4; i++) {           // A: 1024 uint4
            int f = tid + 256 * i;
            int row = f >> 3, u = f & 7;
            uint32_t so = (row << 7) + (((u ^ (row & 7))) << 4);
            size_t gi = (size_t)(c * MTOT + mBase + row) * 8 + u;
            cp16(as + so, Ag + gi);
        }
#pragma unroll
        for (int i = 0; i < 4; i++) {           // B: 1024 uint4
            int f = tid + 256 * i;
            int n = f >> 3, u = f & 7;
            uint32_t so = (n << 7) + (((u ^ (n & 7))) << 4);
            size_t gi = (size_t)(c * N + nBase + n) * 8 + u;
            cp16(bs + so, Bg + gi);
        }
        asm volatile("cp.async.commit_group;" ::: "memory");
    };

    loadChunk(0, smem);

    for (int c = 0; c < 4; c++) {
        char* buf = smem + (c & 1) * BUF;
        if (c < 3) loadChunk(c + 1, smem + ((c + 1) & 1) * BUF);
        if (c < 3) asm volatile("cp.async.wait_group 1;" ::: "memory");
        else       asm volatile("cp.async.wait_group 0;" ::: "memory");
        __syncthreads();

        const uint32_t As = smem_u32(buf);
        const uint32_t Bs = As + O_B;

#pragma unroll
        for (int kk = 0; kk < 4; kk++) {
            uint32_t ah[2][4];
#pragma unroll
            for (int mi = 0; mi < 2; mi++) {
                int r = warpM + mi * 16 + (lane & 15);
                int u = kk * 2 + (lane >> 4);
                uint32_t off = (r << 7) + (((u ^ (r & 7))) << 4);
                ldsm4(ah[mi], As + off);
            }
            uint32_t bh[8][2];
#pragma unroll
            for (int p = 0; p < 4; p++) {
                int r = warpN + p * 16 + ((lane >> 4) << 3) + (lane & 7);
                int u = kk * 2 + ((lane >> 3) & 1);
                uint32_t off = (r << 7) + (((u ^ (r & 7))) << 4);
                ldsm4(&bh[p * 2][0], Bs + off);
            }
#pragma unroll
            for (int mi = 0; mi < 2; mi++)
#pragma unroll
                for (int nj = 0; nj < 8; nj++)
                    mma16816(acc[mi][nj], ah[mi], bh[nj]);
        }
        __syncthreads();
    }

#pragma unroll
    for (int mi = 0; mi < 2; mi++) {
        int row0 = mBase + warpM + mi * 16 + (lane >> 2);
#pragma unroll
        for (int nj = 0; nj < 8; nj++) {
            int col = nBase + warpN + nj * 8 + (lane & 3) * 2;
            float bx = __ldg(bias + col), by = __ldg(bias + col + 1);
            float v00 = acc[mi][nj][0] + bx, v01 = acc[mi][nj][1] + by;
            float v10 = acc[mi][nj][2] + bx, v11 = acc[mi][nj][3] + by;
            if constexpr (sizeof(OutT) == 4) {
                *(float2*)((float*)C + (size_t)row0 * N + col)       = make_float2(v00, v01);
                *(float2*)((float*)C + (size_t)(row0 + 8) * N + col) = make_float2(v10, v11);
            } else {
                *(__half2*)((__half*)C + (size_t)row0 * N + col)       = __floats2half2_rn(v00, v01);
                *(__half2*)((__half*)C + (size_t)(row0 + 8) * N + col) = __floats2half2_rn(v10, v11);
            }
        }
    }
}

// ---------------------------------------------------------------------------
// Fused softmax + deformable sampling (proven R5 structure).
// ---------------------------------------------------------------------------
__global__ __launch_bounds__(256) void msda_sample(const float* __restrict__ refp)
{
    __shared__ float4 sw[16][17];
    __shared__ int4   si[16][17];

    const int tid = threadIdx.x;
    const int rowBase = blockIdx.x * 2;

    // ---- Phase 1: per-(head,point) setup ----
    {
        const int hs  = tid >> 4;        // head slot 0..15
        const int s   = tid & 15;        // point (lvl*4 + pt)
        const int row = rowBase + (hs >> 3);
        const int h   = hs & 7;
        const int b   = row / LQ;

        const int lvl = s >> 2;
        const int Wl  = 64 >> lvl;
        const int st  = (16384 - (16384 >> (2 * lvl))) / 3;

        const float refx = refp[row * 8 + lvl * 2 + 0];
        const float refy = refp[row * 8 + lvl * 2 + 1];
        const int obase  = row * 384 + ((h * 16 + s) * 2);
        const float offx = g_oa[obase + 0];
        const float offy = g_oa[obase + 1];

        const float x = refx * (float)Wl + offx - 0.5f;
        const float y = refy * (float)Wl + offy - 0.5f;
        const float fx = floorf(x), fy = floorf(y);
        const float lx = x - fx,   ly = y - fy;
        const int x0 = (int)fx, y0 = (int)fy;
        const int x1 = x0 + 1,  y1 = y0 + 1;

        const float logit = g_oa[row * 384 + 256 + h * 16 + s];
        float mx = logit;
#pragma unroll
        for (int o = 8; o; o >>= 1) mx = fmaxf(mx, __shfl_xor_sync(~0u, mx, o, 16));
        const float e = __expf(logit - mx);
        float sum = e;
#pragma unroll
        for (int o = 8; o; o >>= 1) sum += __shfl_xor_sync(~0u, sum, o, 16);
        const float wa = e / sum;

        const bool vx0 = (unsigned)x0 < (unsigned)Wl;
        const bool vx1 = (unsigned)x1 < (unsigned)Wl;
        const bool vy0 = (unsigned)y0 < (unsigned)Wl;
        const bool vy1 = (unsigned)y1 < (unsigned)Wl;
        const int cx0 = min(max(x0, 0), Wl - 1);
        const int cx1 = min(max(x1, 0), Wl - 1);
        const int cy0 = min(max(y0, 0), Wl - 1);
        const int cy1 = min(max(y1, 0), Wl - 1);
        const int rb  = b * LIN + st;

        si[hs][s] = make_int4(rb + cy0 * Wl + cx0, rb + cy0 * Wl + cx1,
                              rb + cy1 * Wl + cx0, rb + cy1 * Wl + cx1);
        sw[hs][s] = make_float4(
            wa * (1.f - lx) * (1.f - ly) * (float)(vx0 && vy0),
            wa * lx         * (1.f - ly) * (float)(vx1 && vy0),
            wa * (1.f - lx) * ly         * (float)(vx0 && vy1),
            wa * lx         * ly         * (float)(vx1 && vy1));
    }
    __syncthreads();

    // ---- Phase 2: gather + accumulate ----
    const int wid  = tid >> 5;
    const int lane = tid & 31;
    const int hs   = wid * 2 + (lane >> 4);
    const int row  = rowBase + (hs >> 3);
    const int h    = hs & 7;
    const int c2   = (lane & 15) * 2;          // channel pair

    const __half* __restrict__ vp = g_value_h + h * 32 + c2;
    float ax = 0.f, ay = 0.f;
#pragma unroll 4
    for (int t = 0; t < 16; t++) {
        const float4 w  = sw[hs][t];
        const int4   id = si[hs][t];
        const float2 f0 = __half22float2(*(const __half2*)(vp + (size_t)id.x * 256));
        const float2 f1 = __half22float2(*(const __half2*)(vp + (size_t)id.y * 256));
        const float2 f2 = __half22float2(*(const __half2*)(vp + (size_t)id.z * 256));
        const float2 f3 = __half22float2(*(const __half2*)(vp + (size_t)id.w * 256));
        ax += w.x * f0.x + w.y * f1.x + w.z * f2.x + w.w * f3.x;
        ay += w.x * f0.y + w.y * f1.y + w.z * f2.y + w.w * f3.y;
    }

    // single fp16 core in out-GEMM chunk layout (k = h*32 + c2)
    size_t o = ((size_t)(h >> 1) * MTOT + row) * 64 + (h & 1) * 32 + c2;
    *(__half2*)(g_core_h + o) = __floats2half2_rn(ax, ay);
}

// ---------------------------------------------------------------------------
extern "C" void kernel_launch(void* const* d_in, const int* in_sizes, int n_in,
                              void* d_out, int out_size)
{
    const float* query  = (const float*)d_in[0];
    const float* refp   = (const float*)d_in[1];
    const float* inpf   = (const float*)d_in[2];
    const float* W_val  = (const float*)d_in[5];
    const float* b_val  = (const float*)d_in[6];
    const float* W_off  = (const float*)d_in[7];
    const float* b_off  = (const float*)d_in[8];
    const float* W_attn = (const float*)d_in[9];
    const float* b_attn = (const float*)d_in[10];
    const float* W_out  = (const float*)d_in[11];
    const float* b_out  = (const float*)d_in[12];
    float* out = (float*)d_out;

    __half *p_val, *p_core, *p_if, *p_q;  float *p_oa, *p_boa;
    cudaGetSymbolAddress((void**)&p_val,  g_value_h);
    cudaGetSymbolAddress((void**)&p_oa,   g_oa);
    cudaGetSymbolAddress((void**)&p_boa,  g_boa);
    cudaGetSymbolAddress((void**)&p_core, g_core_h);
    cudaGetSymbolAddress((void**)&p_if,   g_if_h);
    cudaGetSymbolAddress((void**)&p_q,    g_q_h);
    __half *wv, *woa, *wu;
    cudaGetSymbolAddress((void**)&wv,  g_wv);
    cudaGetSymbolAddress((void**)&woa, g_woa);
    cudaGetSymbolAddress((void**)&wu,  g_wu);

    constexpr int SMEM = 65536;
    cudaFuncSetAttribute(gemm_f16<256, __half>, cudaFuncAttributeMaxDynamicSharedMemorySize, SMEM);
    cudaFuncSetAttribute(gemm_f16<384, float>,  cudaFuncAttributeMaxDynamicSharedMemorySize, SMEM);
    cudaFuncSetAttribute(gemm_f16<256, float>,  cudaFuncAttributeMaxDynamicSharedMemorySize, SMEM);

    prep_all<<<896, 256>>>(W_val, W_off, W_attn, W_out, b_off, b_attn);
    // 2 tensors x 4 chunks x MTOT rows x 8 u-groups / 256 = 10880 blocks
    convert_act<<<10880, 256>>>(inpf, query);

    const int MT = MTOT / 128;  // 340
    gemm_f16<256, __half><<<dim3(2, MT), 256, SMEM>>>(p_if, wv,  b_val, p_val);
    gemm_f16<384, float ><<<dim3(3, MT), 256, SMEM>>>(p_q,  woa, p_boa, p_oa);

    msda_sample<<<MTOT / 2, 256>>>(refp);

    gemm_f16<256, float ><<<dim3(2, MT), 256, SMEM>>>(p_core, wu, b_out, out);
}

// round 13
// speedup vs baseline: 2.5724x; 1.0179x over previous
#include <cuda_runtime.h>
#include <cuda_bf16.h>
#include <cuda_fp16.h>
#include <cstdint>

// Problem constants (fixed by the dataset)
#define BB   8
#define LQ   5440
#define LIN  5440
#define DM   256
#define NH   8
#define MTOT (BB * LQ)   // 43520

// ---------------------------------------------------------------------------
// Scratch (device globals; allocation-free per harness rules)
// ---------------------------------------------------------------------------
__device__ __align__(16) __half g_value_h[MTOT * DM];       // fp16 value
__device__ __align__(16) float  g_oa  [MTOT * 384];         // off(256) + attn logits(128)
// fp16 activations in chunk-contiguous GEMM layout:
// half index = ((k>>6)*MTOT + row)*64 + (k&63)
__device__ __align__(16) __half g_core_h[MTOT * DM];
__device__ __align__(16) __half g_if_h  [MTOT * DM];        // inpf fp16
__device__ __align__(16) __half g_q_h   [MTOT * DM];        // query fp16

// Pre-transposed fp16 weights, chunk-contiguous layout:
// element index = ((k>>6)*N + n)*64 + (k&63)   (64-wide K chunks)
__device__ __align__(16) __half g_wv [DM * DM];
__device__ __align__(16) __half g_woa[DM * 384];
__device__ __align__(16) __half g_wu [DM * DM];
__device__ __align__(16) float g_boa[384];

// ---------------------------------------------------------------------------
// Helpers
// ---------------------------------------------------------------------------
__device__ __forceinline__ uint32_t smem_u32(const void* p) {
    uint32_t a;
    asm("{ .reg .u64 t; cvta.to.shared.u64 t, %1; cvt.u32.u64 %0, t; }"
        : "=r"(a) : "l"(p));
    return a;
}
__device__ __forceinline__ void ldsm4(uint32_t* d, uint32_t addr) {
    asm volatile("ldmatrix.sync.aligned.m8n8.x4.shared.b16 {%0,%1,%2,%3}, [%4];"
                 : "=r"(d[0]), "=r"(d[1]), "=r"(d[2]), "=r"(d[3]) : "r"(addr));
}
__device__ __forceinline__ void mma16816(float* c, const uint32_t* a,
                                         const uint32_t* b) {
    asm volatile(
        "mma.sync.aligned.m16n8k16.row.col.f32.f16.f16.f32 "
        "{%0,%1,%2,%3}, {%4,%5,%6,%7}, {%8,%9}, {%0,%1,%2,%3};"
        : "+f"(c[0]), "+f"(c[1]), "+f"(c[2]), "+f"(c[3])
        : "r"(a[0]), "r"(a[1]), "r"(a[2]), "r"(a[3]), "r"(b[0]), "r"(b[1]));
}
__device__ __forceinline__ void cp16(uint32_t dst, const void* src) {
    asm volatile("cp.async.cg.shared.global [%0], [%1], 16;"
                 :: "r"(dst), "l"(src) : "memory");
}

// ---------------------------------------------------------------------------
// Weight prep (transpose + fp16, chunk layout) + combined bias
// ---------------------------------------------------------------------------
__global__ void prep_all(const float* __restrict__ W_val,
                         const float* __restrict__ W_off,
                         const float* __restrict__ W_attn,
                         const float* __restrict__ W_out,
                         const float* __restrict__ b_off,
                         const float* __restrict__ b_attn)
{
    int idx = blockIdx.x * 256 + threadIdx.x;
    if (idx < 384)
        g_boa[idx] = idx < 256 ? b_off[idx] : b_attn[idx - 256];

    float v; __half* w; int o;
    if (idx < 65536) {                       // W_val [256x256]
        int k = idx >> 8, n = idx & 255;
        v = W_val[idx];
        o = (((k >> 6) << 8) + n) * 64 + (k & 63);
        w = g_wv;
    } else if (idx < 65536 + 98304) {        // combined [256x384]
        int t = idx - 65536;
        int k = t / 384, n = t - k * 384;
        v = n < 256 ? W_off[k * 256 + n] : W_attn[k * 128 + (n - 256)];
        o = ((k >> 6) * 384 + n) * 64 + (k & 63);
        w = g_woa;
    } else {                                 // W_out [256x256]
        int t = idx - 65536 - 98304;
        int k = t >> 8, n = t & 255;
        v = W_out[t];
        o = (((k >> 6) << 8) + n) * 64 + (k & 63);
        w = g_wu;
    }
    w[o] = __float2half_rn(v);
}

// ---------------------------------------------------------------------------
// Activation convert: inpf + query fp32 -> fp16 chunk-contiguous layout.
// ---------------------------------------------------------------------------
__global__ __launch_bounds__(256) void convert_act(
    const float* __restrict__ inpf, const float* __restrict__ query)
{
    const int t  = blockIdx.x * 256 + threadIdx.x;
    const int u  = t & 7;
    const int q  = t >> 3;
    const int row = q % MTOT;
    const int cc  = q / MTOT;          // 0..7
    const int c   = cc & 3;
    const float* src = (cc < 4) ? inpf : query;
    __half* dst      = (cc < 4) ? g_if_h : g_q_h;

    const float4* sp = (const float4*)(src + (size_t)row * 256 + c * 64 + u * 8);
    float4 v0 = sp[0], v1 = sp[1];
    __half2 h[4];
    h[0] = __floats2half2_rn(v0.x, v0.y);
    h[1] = __floats2half2_rn(v0.z, v0.w);
    h[2] = __floats2half2_rn(v1.x, v1.y);
    h[3] = __floats2half2_rn(v1.z, v1.w);
    *(uint4*)(dst + ((size_t)c * MTOT + row) * 64 + u * 8) = *(uint4*)h;
}

// ---------------------------------------------------------------------------
// Fused val+oa GEMM, 3-stage cp.async pipeline, one sync per chunk.
// grid (5, 340): bx<2 -> value GEMM (A=g_if_h, B=g_wv, N=256, C fp16);
//                bx>=2 -> off+attn GEMM (A=g_q_h, B=g_woa, N=384, C fp32).
// CTA 128x128, 256 thr, warp tile 32x64. SMEM 3 x 32KB = 96KB (2 CTA/SM).
// ---------------------------------------------------------------------------
__global__ __launch_bounds__(256, 2) void gemm_dual(
    const float* __restrict__ b_val)
{
    extern __shared__ char smem[];
    constexpr int BUF = 32768, O_B = 16384;

    const int tid  = threadIdx.x;
    const int wid  = tid >> 5;
    const int lane = tid & 31;
    const int mBase = blockIdx.y * 128;
    const bool isVal = blockIdx.x < 2;
    const int N     = isVal ? 256 : 384;
    const int nBase = (isVal ? blockIdx.x : blockIdx.x - 2) * 128;
    const int warpM = (wid & 3) * 32;
    const int warpN = (wid >> 2) * 64;

    const uint4* Ag = (const uint4*)(isVal ? g_if_h : g_q_h);
    const uint4* Bg = (const uint4*)(isVal ? g_wv  : g_woa);
    const float* bias = isVal ? b_val : g_boa;

    float acc[2][8][4];
#pragma unroll
    for (int i = 0; i < 2; i++)
#pragma unroll
        for (int j = 0; j < 8; j++)
#pragma unroll
            for (int k = 0; k < 4; k++) acc[i][j][k] = 0.f;

    auto loadChunk = [&](int c, int s) {
        uint32_t as = smem_u32(smem + s * BUF);
        uint32_t bs = as + O_B;
#pragma unroll
        for (int i = 0; i < 4; i++) {           // A: 1024 uint4
            int f = tid + 256 * i;
            int row = f >> 3, u = f & 7;
            uint32_t so = (row << 7) + (((u ^ (row & 7))) << 4);
            size_t gi = (size_t)(c * MTOT + mBase + row) * 8 + u;
            cp16(as + so, Ag + gi);
        }
#pragma unroll
        for (int i = 0; i < 4; i++) {           // B: 1024 uint4
            int f = tid + 256 * i;
            int n = f >> 3, u = f & 7;
            uint32_t so = (n << 7) + (((u ^ (n & 7))) << 4);
            size_t gi = (size_t)(c * N + nBase + n) * 8 + u;
            cp16(bs + so, Bg + gi);
        }
        asm volatile("cp.async.commit_group;" ::: "memory");
    };

    loadChunk(0, 0);
    loadChunk(1, 1);

    for (int c = 0; c < 4; c++) {
        if (c < 3) asm volatile("cp.async.wait_group 1;" ::: "memory");
        else       asm volatile("cp.async.wait_group 0;" ::: "memory");
        __syncthreads();
        if (c < 2) loadChunk(c + 2, (c + 2) % 3);   // writes stage (c-1)%3: safe

        const uint32_t As = smem_u32(smem + (c % 3) * BUF);
        const uint32_t Bs = As + O_B;

#pragma unroll
        for (int kk = 0; kk < 4; kk++) {
            uint32_t ah[2][4];
#pragma unroll
            for (int mi = 0; mi < 2; mi++) {
                int r = warpM + mi * 16 + (lane & 15);
                int u = kk * 2 + (lane >> 4);
                uint32_t off = (r << 7) + (((u ^ (r & 7))) << 4);
                ldsm4(ah[mi], As + off);
            }
            uint32_t bh[8][2];
#pragma unroll
            for (int p = 0; p < 4; p++) {
                int r = warpN + p * 16 + ((lane >> 4) << 3) + (lane & 7);
                int u = kk * 2 + ((lane >> 3) & 1);
                uint32_t off = (r << 7) + (((u ^ (r & 7))) << 4);
                ldsm4(&bh[p * 2][0], Bs + off);
            }
#pragma unroll
            for (int mi = 0; mi < 2; mi++)
#pragma unroll
                for (int nj = 0; nj < 8; nj++)
                    mma16816(acc[mi][nj], ah[mi], bh[nj]);
        }
        if (c < 3) __syncthreads();   // readers done before next iter's cp.async
    }

#pragma unroll
    for (int mi = 0; mi < 2; mi++) {
        int row0 = mBase + warpM + mi * 16 + (lane >> 2);
#pragma unroll
        for (int nj = 0; nj < 8; nj++) {
            int col = nBase + warpN + nj * 8 + (lane & 3) * 2;
            float bx = __ldg(bias + col), by = __ldg(bias + col + 1);
            float v00 = acc[mi][nj][0] + bx, v01 = acc[mi][nj][1] + by;
            float v10 = acc[mi][nj][2] + bx, v11 = acc[mi][nj][3] + by;
            if (isVal) {
                *(__half2*)(g_value_h + (size_t)row0 * 256 + col)       = __floats2half2_rn(v00, v01);
                *(__half2*)(g_value_h + (size_t)(row0 + 8) * 256 + col) = __floats2half2_rn(v10, v11);
            } else {
                *(float2*)(g_oa + (size_t)row0 * 384 + col)       = make_float2(v00, v01);
                *(float2*)(g_oa + (size_t)(row0 + 8) * 384 + col) = make_float2(v10, v11);
            }
        }
    }
}

// ---------------------------------------------------------------------------
// Output GEMM (N=256, A=g_core_h fp16 chunk layout), same 3-stage pipeline.
// ---------------------------------------------------------------------------
__global__ __launch_bounds__(256, 2) void gemm_out(
    const float* __restrict__ bias, float* __restrict__ C)
{
    extern __shared__ char smem[];
    constexpr int BUF = 32768, O_B = 16384;
    constexpr int N = 256;

    const int tid  = threadIdx.x;
    const int wid  = tid >> 5;
    const int lane = tid & 31;
    const int mBase = blockIdx.y * 128;
    const int nBase = blockIdx.x * 128;
    const int warpM = (wid & 3) * 32;
    const int warpN = (wid >> 2) * 64;

    const uint4* Ag = (const uint4*)g_core_h;
    const uint4* Bg = (const uint4*)g_wu;

    float acc[2][8][4];
#pragma unroll
    for (int i = 0; i < 2; i++)
#pragma unroll
        for (int j = 0; j < 8; j++)
#pragma unroll
            for (int k = 0; k < 4; k++) acc[i][j][k] = 0.f;

    auto loadChunk = [&](int c, int s) {
        uint32_t as = smem_u32(smem + s * BUF);
        uint32_t bs = as + O_B;
#pragma unroll
        for (int i = 0; i < 4; i++) {
            int f = tid + 256 * i;
            int row = f >> 3, u = f & 7;
            uint32_t so = (row << 7) + (((u ^ (row & 7))) << 4);
            size_t gi = (size_t)(c * MTOT + mBase + row) * 8 + u;
            cp16(as + so, Ag + gi);
        }
#pragma unroll
        for (int i = 0; i < 4; i++) {
            int f = tid + 256 * i;
            int n = f >> 3, u = f & 7;
            uint32_t so = (n << 7) + (((u ^ (n & 7))) << 4);
            size_t gi = (size_t)(c * N + nBase + n) * 8 + u;
            cp16(bs + so, Bg + gi);
        }
        asm volatile("cp.async.commit_group;" ::: "memory");
    };

    loadChunk(0, 0);
    loadChunk(1, 1);

    for (int c = 0; c < 4; c++) {
        if (c < 3) asm volatile("cp.async.wait_group 1;" ::: "memory");
        else       asm volatile("cp.async.wait_group 0;" ::: "memory");
        __syncthreads();
        if (c < 2) loadChunk(c + 2, (c + 2) % 3);

        const uint32_t As = smem_u32(smem + (c % 3) * BUF);
        const uint32_t Bs = As + O_B;

#pragma unroll
        for (int kk = 0; kk < 4; kk++) {
            uint32_t ah[2][4];
#pragma unroll
            for (int mi = 0; mi < 2; mi++) {
                int r = warpM + mi * 16 + (lane & 15);
                int u = kk * 2 + (lane >> 4);
                uint32_t off = (r << 7) + (((u ^ (r & 7))) << 4);
                ldsm4(ah[mi], As + off);
            }
            uint32_t bh[8][2];
#pragma unroll
            for (int p = 0; p < 4; p++) {
                int r = warpN + p * 16 + ((lane >> 4) << 3) + (lane & 7);
                int u = kk * 2 + ((lane >> 3) & 1);
                uint32_t off = (r << 7) + (((u ^ (r & 7))) << 4);
                ldsm4(&bh[p * 2][0], Bs + off);
            }
#pragma unroll
            for (int mi = 0; mi < 2; mi++)
#pragma unroll
                for (int nj = 0; nj < 8; nj++)
                    mma16816(acc[mi][nj], ah[mi], bh[nj]);
        }
        if (c < 3) __syncthreads();
    }

#pragma unroll
    for (int mi = 0; mi < 2; mi++) {
        int row0 = mBase + warpM + mi * 16 + (lane >> 2);
#pragma unroll
        for (int nj = 0; nj < 8; nj++) {
            int col = nBase + warpN + nj * 8 + (lane & 3) * 2;
            float bx = __ldg(bias + col), by = __ldg(bias + col + 1);
            *(float2*)(C + (size_t)row0 * N + col) =
                make_float2(acc[mi][nj][0] + bx, acc[mi][nj][1] + by);
            *(float2*)(C + (size_t)(row0 + 8) * N + col) =
                make_float2(acc[mi][nj][2] + bx, acc[mi][nj][3] + by);
        }
    }
}

// ---------------------------------------------------------------------------
// Fused softmax + deformable sampling (proven R5 structure).
// ---------------------------------------------------------------------------
__global__ __launch_bounds__(256) void msda_sample(const float* __restrict__ refp)
{
    __shared__ float4 sw[16][17];
    __shared__ int4   si[16][17];

    const int tid = threadIdx.x;
    const int rowBase = blockIdx.x * 2;

    // ---- Phase 1: per-(head,point) setup ----
    {
        const int hs  = tid >> 4;        // head slot 0..15
        const int s   = tid & 15;        // point (lvl*4 + pt)
        const int row = rowBase + (hs >> 3);
        const int h   = hs & 7;
        const int b   = row / LQ;

        const int lvl = s >> 2;
        const int Wl  = 64 >> lvl;
        const int st  = (16384 - (16384 >> (2 * lvl))) / 3;

        const float refx = refp[row * 8 + lvl * 2 + 0];
        const float refy = refp[row * 8 + lvl * 2 + 1];
        const int obase  = row * 384 + ((h * 16 + s) * 2);
        const float offx = g_oa[obase + 0];
        const float offy = g_oa[obase + 1];

        const float x = refx * (float)Wl + offx - 0.5f;
        const float y = refy * (float)Wl + offy - 0.5f;
        const float fx = floorf(x), fy = floorf(y);
        const float lx = x - fx,   ly = y - fy;
        const int x0 = (int)fx, y0 = (int)fy;
        const int x1 = x0 + 1,  y1 = y0 + 1;

        const float logit = g_oa[row * 384 + 256 + h * 16 + s];
        float mx = logit;
#pragma unroll
        for (int o = 8; o; o >>= 1) mx = fmaxf(mx, __shfl_xor_sync(~0u, mx, o, 16));
        const float e = __expf(logit - mx);
        float sum = e;
#pragma unroll
        for (int o = 8; o; o >>= 1) sum += __shfl_xor_sync(~0u, sum, o, 16);
        const float wa = e / sum;

        const bool vx0 = (unsigned)x0 < (unsigned)Wl;
        const bool vx1 = (unsigned)x1 < (unsigned)Wl;
        const bool vy0 = (unsigned)y0 < (unsigned)Wl;
        const bool vy1 = (unsigned)y1 < (unsigned)Wl;
        const int cx0 = min(max(x0, 0), Wl - 1);
        const int cx1 = min(max(x1, 0), Wl - 1);
        const int cy0 = min(max(y0, 0), Wl - 1);
        const int cy1 = min(max(y1, 0), Wl - 1);
        const int rb  = b * LIN + st;

        si[hs][s] = make_int4(rb + cy0 * Wl + cx0, rb + cy0 * Wl + cx1,
                              rb + cy1 * Wl + cx0, rb + cy1 * Wl + cx1);
        sw[hs][s] = make_float4(
            wa * (1.f - lx) * (1.f - ly) * (float)(vx0 && vy0),
            wa * lx         * (1.f - ly) * (float)(vx1 && vy0),
            wa * (1.f - lx) * ly         * (float)(vx0 && vy1),
            wa * lx         * ly         * (float)(vx1 && vy1));
    }
    __syncthreads();

    // ---- Phase 2: gather + accumulate ----
    const int wid  = tid >> 5;
    const int lane = tid & 31;
    const int hs   = wid * 2 + (lane >> 4);
    const int row  = rowBase + (hs >> 3);
    const int h    = hs & 7;
    const int c2   = (lane & 15) * 2;          // channel pair

    const __half* __restrict__ vp = g_value_h + h * 32 + c2;
    float ax = 0.f, ay = 0.f;
#pragma unroll 4
    for (int t = 0; t < 16; t++) {
        const float4 w  = sw[hs][t];
        const int4   id = si[hs][t];
        const float2 f0 = __half22float2(*(const __half2*)(vp + (size_t)id.x * 256));
        const float2 f1 = __half22float2(*(const __half2*)(vp + (size_t)id.y * 256));
        const float2 f2 = __half22float2(*(const __half2*)(vp + (size_t)id.z * 256));
        const float2 f3 = __half22float2(*(const __half2*)(vp + (size_t)id.w * 256));
        ax += w.x * f0.x + w.y * f1.x + w.z * f2.x + w.w * f3.x;
        ay += w.x * f0.y + w.y * f1.y + w.z * f2.y + w.w * f3.y;
    }

    // single fp16 core in out-GEMM chunk layout (k = h*32 + c2)
    size_t o = ((size_t)(h >> 1) * MTOT + row) * 64 + (h & 1) * 32 + c2;
    *(__half2*)(g_core_h + o) = __floats2half2_rn(ax, ay);
}

// ---------------------------------------------------------------------------
extern "C" void kernel_launch(void* const* d_in, const int* in_sizes, int n_in,
                              void* d_out, int out_size)
{
    const float* query  = (const float*)d_in[0];
    const float* refp   = (const float*)d_in[1];
    const float* inpf   = (const float*)d_in[2];
    const float* W_val  = (const float*)d_in[5];
    const float* b_val  = (const float*)d_in[6];
    const float* W_off  = (const float*)d_in[7];
    const float* b_off  = (const float*)d_in[8];
    const float* W_attn = (const float*)d_in[9];
    const float* b_attn = (const float*)d_in[10];
    const float* W_out  = (const float*)d_in[11];
    const float* b_out  = (const float*)d_in[12];
    float* out = (float*)d_out;

    constexpr int SMEM = 98304;   // 3 x 32KB
    cudaFuncSetAttribute(gemm_dual, cudaFuncAttributeMaxDynamicSharedMemorySize, SMEM);
    cudaFuncSetAttribute(gemm_out,  cudaFuncAttributeMaxDynamicSharedMemorySize, SMEM);

    prep_all<<<896, 256>>>(W_val, W_off, W_attn, W_out, b_off, b_attn);
    convert_act<<<10880, 256>>>(inpf, query);

    const int MT = MTOT / 128;  // 340
    gemm_dual<<<dim3(5, MT), 256, SMEM>>>(b_val);

    msda_sample<<<MTOT / 2, 256>>>(refp);

    gemm_out<<<dim3(2, MT), 256, SMEM>>>(b_out, out);
}